// round 13
// baseline (speedup 1.0000x reference)
#include <cuda_runtime.h>
#include <math.h>
#include <stdint.h>

// ---------------------------------------------------------------------------
// Problem constants
// ---------------------------------------------------------------------------
#define BATCH   2
#define SEQ     4096
#define DMODEL  1024
#define DINNER  2048
#define NHEADS  16
#define HDIM    128
#define DSTATE  16
#define DCONV   4
#define CHUNK   64
#define NCHUNK  (SEQ / CHUNK)      // 64
#define M_ROWS  (BATCH * SEQ)      // 8192
#define NPROJ   (NHEADS + 2*DSTATE) // 48
#define ROWW    (2 * DINNER)        // g_xz row width
#define LN_EPS  1e-5f

// Pipelined GEMM config: BM=128, BN=256, BK=16, 8 warps of 64x64
#define PSTAGES    4
#define AS_STRIDE  20                 // padded row pitch (floats)
#define BS_STRIDE  264                // 256 + 8 pad (floats)
#define AS_STAGE   (128 * AS_STRIDE)  // 2560 floats
#define BS_STAGE   (16 * BS_STRIDE)   // 4224 floats
#define PIPE_SMEM_BYTES ((PSTAGES * (AS_STAGE + BS_STAGE)) * 4)  // 108544 B

// ---------------------------------------------------------------------------
// Scratch (static device globals -- no allocation allowed)
// ---------------------------------------------------------------------------
__device__ float  g_xz[(size_t)M_ROWS * ROWW];          // [xe | z]
__device__ float  g_proj[(size_t)M_ROWS * NPROJ];       // dt_raw | B | C
__device__ float  g_y[(size_t)M_ROWS * DINNER];         // raw gated y (pre-LN)
__device__ float  g_yn[(size_t)M_ROWS * DINNER];        // tf32-rounded LN(y)
__device__ float  g_S[(size_t)BATCH*NHEADS*NCHUNK*HDIM*DSTATE];   // chunk-local states
__device__ float  g_Sin[(size_t)BATCH*NHEADS*NCHUNK*HDIM*DSTATE]; // incoming states
__device__ float  g_P[(size_t)BATCH*NHEADS*NCHUNK*HDIM];
__device__ float  g_xr [(size_t)M_ROWS * DMODEL];       // tf32-rounded x
__device__ float  g_w1r[(size_t)DMODEL * 2 * DINNER];   // tf32-rounded W_in
__device__ float  g_w2r[(size_t)DINNER * DMODEL];       // tf32-rounded W_out

// ---------------------------------------------------------------------------
// Helpers
// ---------------------------------------------------------------------------
__device__ __forceinline__ uint32_t tf32_rn(float x) {
    uint32_t r;
    asm("cvt.rna.tf32.f32 %0, %1;" : "=r"(r) : "f"(x));
    return r;
}
__device__ __forceinline__ float4 round4(float4 v) {
    v.x = __uint_as_float(tf32_rn(v.x));
    v.y = __uint_as_float(tf32_rn(v.y));
    v.z = __uint_as_float(tf32_rn(v.z));
    v.w = __uint_as_float(tf32_rn(v.w));
    return v;
}
__device__ __forceinline__ void mma_tf32(float* c, const uint32_t* a, const uint32_t* b) {
    asm volatile(
        "mma.sync.aligned.m16n8k8.row.col.f32.tf32.tf32.f32 "
        "{%0,%1,%2,%3},{%4,%5,%6,%7},{%8,%9},{%0,%1,%2,%3};"
        : "+f"(c[0]), "+f"(c[1]), "+f"(c[2]), "+f"(c[3])
        : "r"(a[0]), "r"(a[1]), "r"(a[2]), "r"(a[3]), "r"(b[0]), "r"(b[1]));
}
__device__ __forceinline__ float softplus_acc(float x) {
    return (x > 20.f) ? x : log1pf(expf(x));
}
__device__ __forceinline__ float silu_acc(float v) {
    return v / (1.f + expf(-v));
}
__device__ __forceinline__ float4 ln_apply(float4 v, float mu, float rs,
                                           const float* __restrict__ g,
                                           const float* __restrict__ b, int col) {
    float4 gg = *(const float4*)(g + col);
    float4 bb = *(const float4*)(b + col);
    v.x = (v.x - mu) * rs * gg.x + bb.x;
    v.y = (v.y - mu) * rs * gg.y + bb.y;
    v.z = (v.z - mu) * rs * gg.z + bb.z;
    v.w = (v.w - mu) * rs * gg.w + bb.w;
    return v;
}
__device__ __forceinline__ void cp_async16(const void* smem_dst, const void* gmem_src) {
    uint32_t sa = (uint32_t)__cvta_generic_to_shared(smem_dst);
    asm volatile("cp.async.cg.shared.global [%0], [%1], 16;"
                 :: "r"(sa), "l"(gmem_src) : "memory");
}
#define CP_COMMIT()  asm volatile("cp.async.commit_group;" ::: "memory")
#define CP_WAIT2()   asm volatile("cp.async.wait_group 2;" ::: "memory")

// ---------------------------------------------------------------------------
// Elementwise tf32 pre-round: dst = round_tf32(src). n multiple of 4.
// ---------------------------------------------------------------------------
__global__ __launch_bounds__(256) void round_tf32_kernel(
    const float* __restrict__ src, float* __restrict__ dst, int n4)
{
    int i = blockIdx.x * 256 + threadIdx.x;
    if (i < n4)
        *(float4*)(dst + 4 * (size_t)i) = round4(*(const float4*)(src + 4 * (size_t)i));
}

// ---------------------------------------------------------------------------
// Pipelined TF32 GEMM, cvt-free, BM=128 BN=256 BK=16, warp tile 64x64.
// C[M,N] = A[M,K] @ B[K,N]. M%128==0, N%256==0, K%16==0.
// Per-element accumulation chain identical to previous configs.
// ---------------------------------------------------------------------------
__global__ __launch_bounds__(256, 1) void gemm_tf32_pipe(
    const float* __restrict__ A, const float* __restrict__ B,
    float* __restrict__ C, int M, int N, int K)
{
    extern __shared__ __align__(16) float smem[];
    float* As = smem;                          // [PSTAGES][128][AS_STRIDE]
    float* Bs = smem + PSTAGES * AS_STAGE;     // [PSTAGES][16][BS_STRIDE]

    const int tid  = threadIdx.x;
    const int warp = tid >> 5, lane = tid & 31;
    const int g    = lane >> 2, q = lane & 3;
    const int wm   = (warp & 1) * 64;          // 2 warps over M
    const int wn   = (warp >> 1) * 64;         // 4 warps over N
    const int m0   = blockIdx.y * 128;
    const int n0   = blockIdx.x * 256;

    const int ar = tid >> 1;            // A row 0..127
    const int ac = (tid & 1) * 8;       // A col 0 or 8
    const int br = tid >> 4;            // B row 0..15
    const int bc = (tid & 15) * 16;     // B col 0..240

    const float* Abase = A + (size_t)(m0 + ar) * K + ac;
    const float* Bbase = B + (size_t)br * N + n0 + bc;

    const int nk = K >> 4;

    // prefill stages 0..2
#pragma unroll
    for (int s = 0; s < PSTAGES - 1; s++) {
        if (s < nk) {
            const float* Ap = Abase + s * 16;
            const float* Bp = Bbase + (size_t)s * 16 * N;
            float* Ad = As + s * AS_STAGE + ar * AS_STRIDE + ac;
            float* Bd = Bs + s * BS_STAGE + br * BS_STRIDE + bc;
            cp_async16(Ad,      Ap);
            cp_async16(Ad + 4,  Ap + 4);
            cp_async16(Bd,      Bp);
            cp_async16(Bd + 4,  Bp + 4);
            cp_async16(Bd + 8,  Bp + 8);
            cp_async16(Bd + 12, Bp + 12);
        }
        CP_COMMIT();
    }

    float acc[4][8][4];
#pragma unroll
    for (int i = 0; i < 4; i++)
#pragma unroll
        for (int j = 0; j < 8; j++)
#pragma unroll
            for (int k = 0; k < 4; k++) acc[i][j][k] = 0.f;

    for (int kt = 0; kt < nk; kt++) {
        CP_WAIT2();
        __syncthreads();

        {
            const int kf = kt + PSTAGES - 1;
            if (kf < nk) {
                const int s = kf & (PSTAGES - 1);
                const float* Ap = Abase + kf * 16;
                const float* Bp = Bbase + (size_t)kf * 16 * N;
                float* Ad = As + s * AS_STAGE + ar * AS_STRIDE + ac;
                float* Bd = Bs + s * BS_STAGE + br * BS_STRIDE + bc;
                cp_async16(Ad,      Ap);
                cp_async16(Ad + 4,  Ap + 4);
                cp_async16(Bd,      Bp);
                cp_async16(Bd + 4,  Bp + 4);
                cp_async16(Bd + 8,  Bp + 8);
                cp_async16(Bd + 12, Bp + 12);
            }
            CP_COMMIT();
        }

        const float* Ac = As + (kt & (PSTAGES - 1)) * AS_STAGE;
        const float* Bc = Bs + (kt & (PSTAGES - 1)) * BS_STAGE;

#pragma unroll
        for (int ks = 0; ks < 2; ks++) {
            uint32_t af[4][4], bf[8][2];
            const int kk = ks * 8 + q;
#pragma unroll
            for (int tm = 0; tm < 4; tm++) {
                const int r = wm + tm * 16 + g;
                af[tm][0] = __float_as_uint(Ac[r * AS_STRIDE + kk]);
                af[tm][1] = __float_as_uint(Ac[(r + 8) * AS_STRIDE + kk]);
                af[tm][2] = __float_as_uint(Ac[r * AS_STRIDE + kk + 4]);
                af[tm][3] = __float_as_uint(Ac[(r + 8) * AS_STRIDE + kk + 4]);
            }
#pragma unroll
            for (int tn = 0; tn < 8; tn++) {
                const int n = wn + tn * 8 + g;
                bf[tn][0] = __float_as_uint(Bc[kk * BS_STRIDE + n]);
                bf[tn][1] = __float_as_uint(Bc[(kk + 4) * BS_STRIDE + n]);
            }
#pragma unroll
            for (int tm = 0; tm < 4; tm++)
#pragma unroll
                for (int tn = 0; tn < 8; tn++)
                    mma_tf32(acc[tm][tn], af[tm], bf[tn]);
        }
    }

#pragma unroll
    for (int tm = 0; tm < 4; tm++) {
        const int row = m0 + wm + tm * 16 + g;
#pragma unroll
        for (int tn = 0; tn < 8; tn++) {
            const int col = n0 + wn + tn * 8 + 2 * q;
            *(float2*)&C[(size_t)row * N + col] =
                make_float2(acc[tm][tn][0], acc[tm][tn][1]);
            *(float2*)&C[(size_t)(row + 8) * N + col] =
                make_float2(acc[tm][tn][2], acc[tm][tn][3]);
        }
    }
}

// ---------------------------------------------------------------------------
// proj + fused depthwise conv + silu.
// ---------------------------------------------------------------------------
__global__ __launch_bounds__(256) void proj_conv_kernel(
    const float* __restrict__ W_xproj, const float* __restrict__ conv_w,
    const float* __restrict__ conv_b)
{
    __shared__ float xr[35][64];
    __shared__ float ws[64][NPROJ];
    __shared__ float xs[32][64];
    const int tid = threadIdx.x;
    const int m0  = blockIdx.x * 32;
    const bool seqstart = ((m0 & (SEQ - 1)) == 0);

    float acc[6];
#pragma unroll
    for (int o = 0; o < 6; o++) acc[o] = 0.f;

    for (int k0 = 0; k0 < DINNER; k0 += 64) {
        for (int t = tid; t < 35 * 64; t += 256) {
            int rr = t >> 6, cc = t & 63;
            float v = 0.f;
            if (!(seqstart && rr < 3))
                v = g_xz[(size_t)(m0 - 3 + rr) * ROWW + k0 + cc];
            xr[rr][cc] = v;
        }
        for (int t = tid; t < 64 * NPROJ; t += 256) {
            int kk = t / NPROJ;
            int j  = t - kk * NPROJ;
            ws[kk][j] = W_xproj[(size_t)(k0 + kk) * NPROJ + j];
        }
        __syncthreads();

        for (int t = tid; t < 32 * 64; t += 256) {
            int r  = t >> 6, cc = t & 63;
            int ch = k0 + cc;
            float4 wv = *(const float4*)(conv_w + (size_t)ch * 4);
            float a = conv_b[ch];
            a = fmaf(wv.x, xr[r][cc],     a);
            a = fmaf(wv.y, xr[r + 1][cc], a);
            a = fmaf(wv.z, xr[r + 2][cc], a);
            a = fmaf(wv.w, xr[r + 3][cc], a);
            xs[r][cc] = silu_acc(a);
        }
        __syncthreads();

#pragma unroll
        for (int o = 0; o < 6; o++) {
            int oi = o * 256 + tid;
            int r  = oi / NPROJ;
            int j  = oi - r * NPROJ;
            float a = acc[o];
#pragma unroll 8
            for (int kk = 0; kk < 64; kk++)
                a = fmaf(xs[r][kk], ws[kk][j], a);
            acc[o] = a;
        }
        __syncthreads();
    }
#pragma unroll
    for (int o = 0; o < 6; o++) {
        int oi = o * 256 + tid;
        int r  = oi / NPROJ;
        int j  = oi - r * NPROJ;
        g_proj[(size_t)(m0 + r) * NPROJ + j] = acc[o];
    }
}

// ---------------------------------------------------------------------------
// Chunked scan, pass 1: rolling-window conv+silu, dt/decay on the fly.
// g_P is the PRODUCT of all 64 per-step decays.
// ---------------------------------------------------------------------------
__global__ __launch_bounds__(128) void scan_pass1(
    const float* __restrict__ W_dt, const float* __restrict__ b_dt,
    const float* __restrict__ A_log, const float* __restrict__ conv_w,
    const float* __restrict__ conv_b)
{
    const int blk = blockIdx.x;
    const int c   = blk & (NCHUNK - 1);
    const int h   = (blk >> 6) & (NHEADS - 1);
    const int b   = blk >> 10;
    const int d   = threadIdx.x;
    const int i   = h * HDIM + d;

    __shared__ float sB[CHUNK][DSTATE];
    __shared__ float sR[CHUNK][NHEADS];
    for (int t = threadIdx.x; t < CHUNK * DSTATE; t += 128) {
        int tt = t >> 4, n = t & 15;
        size_t pm = (size_t)(b * SEQ + c * CHUNK + tt) * NPROJ;
        sB[tt][n] = g_proj[pm + NHEADS + n];
        sR[tt][n] = g_proj[pm + n];
    }
    __syncthreads();

    float w[NHEADS];
#pragma unroll
    for (int hh = 0; hh < NHEADS; hh++) w[hh] = W_dt[(size_t)hh * DINNER + i];
    const float bd = b_dt[i];
    const float Ah = -expf(A_log[h]);
    const float4 cw = *(const float4*)(conv_w + (size_t)i * 4);
    const float cb = conv_b[i];

    const int mbase = b * SEQ + c * CHUNK;
    float x3 = 0.f, x2 = 0.f, x1 = 0.f;
    if (c > 0) {
        x3 = g_xz[(size_t)(mbase - 3) * ROWW + i];
        x2 = g_xz[(size_t)(mbase - 2) * ROWW + i];
        x1 = g_xz[(size_t)(mbase - 1) * ROWW + i];
    }

    float s[DSTATE];
#pragma unroll
    for (int n = 0; n < DSTATE; n++) s[n] = 0.f;
    float cum = 0.f;
    float P   = 1.f;

    for (int tt = 0; tt < CHUNK; tt++) {
        float raw = bd;
#pragma unroll
        for (int hh = 0; hh < NHEADS; hh++) raw = fmaf(sR[tt][hh], w[hh], raw);
        float dtv = softplus_acc(raw);
        cum += dtv;
        float a = expf(Ah * cum);
        P *= a;

        float x0 = g_xz[(size_t)(mbase + tt) * ROWW + i];
        float cv = cb;
        cv = fmaf(cw.x, x3, cv);
        cv = fmaf(cw.y, x2, cv);
        cv = fmaf(cw.z, x1, cv);
        cv = fmaf(cw.w, x0, cv);
        float xc = silu_acc(cv);
        x3 = x2; x2 = x1; x1 = x0;

        float u = dtv * xc;
#pragma unroll
        for (int n = 0; n < DSTATE; n++)
            s[n] = fmaf(s[n], a, u * sB[tt][n]);
    }
    const int base = ((b * NHEADS + h) * NCHUNK + c) * HDIM + d;
    g_P[base] = P;
#pragma unroll
    for (int n = 0; n < DSTATE; n++) g_S[(size_t)base * DSTATE + n] = s[n];
}

// ---------------------------------------------------------------------------
// Pass 2: stitch across chunks (separate in/out buffers -> pipelined loads).
// ---------------------------------------------------------------------------
__global__ __launch_bounds__(256) void scan_pass2()
{
    const int idx = blockIdx.x * 256 + threadIdx.x;   // BATCH*NHEADS*HDIM*DSTATE
    const int n   = idx & (DSTATE - 1);
    const int d   = (idx >> 4) & (HDIM - 1);
    const int bh  = idx >> 11;                        // 0..31

    float s = 0.f;
#pragma unroll 8
    for (int c = 0; c < NCHUNK; c++) {
        const int base = (bh * NCHUNK + c) * HDIM + d;
        const float Pv = g_P[base];
        const size_t off = (size_t)base * DSTATE + n;
        const float Sl = g_S[off];
        g_Sin[off] = s;               // incoming state for chunk c
        s = fmaf(Pv, s, Sl);
    }
}

// ---------------------------------------------------------------------------
// Pass 3: replay (rolling conv) + y = C.s + D*x, gate with silu(z) -> g_y raw
// ---------------------------------------------------------------------------
__global__ __launch_bounds__(128) void scan_pass3(
    const float* __restrict__ W_dt, const float* __restrict__ b_dt,
    const float* __restrict__ A_log, const float* __restrict__ D_skip,
    const float* __restrict__ conv_w, const float* __restrict__ conv_b)
{
    const int blk = blockIdx.x;
    const int c   = blk & (NCHUNK - 1);
    const int h   = (blk >> 6) & (NHEADS - 1);
    const int b   = blk >> 10;
    const int d   = threadIdx.x;
    const int i   = h * HDIM + d;

    __shared__ float sB[CHUNK][DSTATE];
    __shared__ float sC[CHUNK][DSTATE];
    __shared__ float sR[CHUNK][NHEADS];
    for (int t = threadIdx.x; t < CHUNK * DSTATE; t += 128) {
        int tt = t >> 4, n = t & 15;
        size_t pm = (size_t)(b * SEQ + c * CHUNK + tt) * NPROJ;
        sB[tt][n] = g_proj[pm + NHEADS + n];
        sC[tt][n] = g_proj[pm + NHEADS + DSTATE + n];
        sR[tt][n] = g_proj[pm + n];
    }
    __syncthreads();

    float w[NHEADS];
#pragma unroll
    for (int hh = 0; hh < NHEADS; hh++) w[hh] = W_dt[(size_t)hh * DINNER + i];
    const float bd = b_dt[i];
    const float Ah = -expf(A_log[h]);
    const float Dh = D_skip[h];
    const float4 cw = *(const float4*)(conv_w + (size_t)i * 4);
    const float cb = conv_b[i];

    const int base = ((b * NHEADS + h) * NCHUNK + c) * HDIM + d;
    float s[DSTATE];
#pragma unroll
    for (int n = 0; n < DSTATE; n++) s[n] = g_Sin[(size_t)base * DSTATE + n];

    const int mbase = b * SEQ + c * CHUNK;
    float x3 = 0.f, x2 = 0.f, x1 = 0.f;
    if (c > 0) {
        x3 = g_xz[(size_t)(mbase - 3) * ROWW + i];
        x2 = g_xz[(size_t)(mbase - 2) * ROWW + i];
        x1 = g_xz[(size_t)(mbase - 1) * ROWW + i];
    }

    float cum = 0.f;
    for (int tt = 0; tt < CHUNK; tt++) {
        float raw = bd;
#pragma unroll
        for (int hh = 0; hh < NHEADS; hh++) raw = fmaf(sR[tt][hh], w[hh], raw);
        float dtv = softplus_acc(raw);
        cum += dtv;
        float a = expf(Ah * cum);

        const size_t rowoff = (size_t)(mbase + tt) * ROWW;
        float x0 = g_xz[rowoff + i];
        float cv = cb;
        cv = fmaf(cw.x, x3, cv);
        cv = fmaf(cw.y, x2, cv);
        cv = fmaf(cw.z, x1, cv);
        cv = fmaf(cw.w, x0, cv);
        float xc = silu_acc(cv);
        x3 = x2; x2 = x1; x1 = x0;

        float u = dtv * xc;
        float y = 0.f;
#pragma unroll
        for (int n = 0; n < DSTATE; n++) {
            s[n] = fmaf(s[n], a, u * sB[tt][n]);
            y    = fmaf(s[n], sC[tt][n], y);
        }
        y = fmaf(Dh, xc, y);
        float zv = g_xz[rowoff + DINNER + i];
        y *= silu_acc(zv);
        g_y[(size_t)(mbase + tt) * DINNER + i] = y;
    }
}

// ---------------------------------------------------------------------------
// LayerNorm stats + apply + tf32 round: g_y -> g_yn (ready for cvt-free GEMM2).
// ---------------------------------------------------------------------------
__global__ __launch_bounds__(256) void ln_apply_kernel(
    const float* __restrict__ ln_g, const float* __restrict__ ln_b)
{
    __shared__ float sh[8];
    __shared__ float s_mu, s_rstd;
    const int m   = blockIdx.x;
    const int tid = threadIdx.x;
    const float* row = g_y + (size_t)m * DINNER;
    float* rown = g_yn + (size_t)m * DINNER;

    const int i0 = tid * 4;
    float4 a  = *(const float4*)(row + i0);
    float4 b4 = *(const float4*)(row + 1024 + i0);
    float v[8] = {a.x, a.y, a.z, a.w, b4.x, b4.y, b4.z, b4.w};

    float sum = 0.f;
#pragma unroll
    for (int k = 0; k < 8; k++) sum += v[k];
#pragma unroll
    for (int o = 16; o > 0; o >>= 1) sum += __shfl_xor_sync(0xffffffffu, sum, o);
    if ((tid & 31) == 0) sh[tid >> 5] = sum;
    __syncthreads();
    if (tid < 32) {
        float t = (tid < 8) ? sh[tid] : 0.f;
#pragma unroll
        for (int o = 4; o > 0; o >>= 1) t += __shfl_xor_sync(0xffffffffu, t, o);
        if (tid == 0) s_mu = t * (1.f / (float)DINNER);
    }
    __syncthreads();
    const float mu = s_mu;

    float var = 0.f;
#pragma unroll
    for (int k = 0; k < 8; k++) { float dv = v[k] - mu; var = fmaf(dv, dv, var); }
#pragma unroll
    for (int o = 16; o > 0; o >>= 1) var += __shfl_xor_sync(0xffffffffu, var, o);
    __syncthreads();
    if ((tid & 31) == 0) sh[tid >> 5] = var;
    __syncthreads();
    if (tid < 32) {
        float t = (tid < 8) ? sh[tid] : 0.f;
#pragma unroll
        for (int o = 4; o > 0; o >>= 1) t += __shfl_xor_sync(0xffffffffu, t, o);
        if (tid == 0) s_rstd = rsqrtf(t * (1.f / (float)DINNER) + LN_EPS);
    }
    __syncthreads();
    const float rs = s_rstd;

    float4 lo = make_float4(v[0], v[1], v[2], v[3]);
    float4 hi = make_float4(v[4], v[5], v[6], v[7]);
    *(float4*)(rown + i0)        = round4(ln_apply(lo, mu, rs, ln_g, ln_b, i0));
    *(float4*)(rown + 1024 + i0) = round4(ln_apply(hi, mu, rs, ln_g, ln_b, 1024 + i0));
}

// ---------------------------------------------------------------------------
// kernel_launch
// ---------------------------------------------------------------------------
extern "C" void kernel_launch(void* const* d_in, const int* in_sizes, int n_in,
                              void* d_out, int out_size)
{
    const float* x       = (const float*)d_in[0];
    const float* W_in    = (const float*)d_in[1];
    const float* conv_w  = (const float*)d_in[2];
    const float* conv_b  = (const float*)d_in[3];
    const float* W_xproj = (const float*)d_in[4];
    const float* W_dt    = (const float*)d_in[5];
    const float* b_dt    = (const float*)d_in[6];
    const float* A_log   = (const float*)d_in[7];
    const float* D_skip  = (const float*)d_in[8];
    const float* W_out   = (const float*)d_in[9];
    const float* ln_g    = (const float*)d_in[10];
    const float* ln_b    = (const float*)d_in[11];
    float* out = (float*)d_out;

    float *pxz = nullptr, *pxr = nullptr, *pw1 = nullptr, *pw2 = nullptr, *pyn = nullptr;
    cudaGetSymbolAddress((void**)&pxz, g_xz);
    cudaGetSymbolAddress((void**)&pxr, g_xr);
    cudaGetSymbolAddress((void**)&pw1, g_w1r);
    cudaGetSymbolAddress((void**)&pw2, g_w2r);
    cudaGetSymbolAddress((void**)&pyn, g_yn);

    cudaFuncSetAttribute(gemm_tf32_pipe,
                         cudaFuncAttributeMaxDynamicSharedMemorySize,
                         PIPE_SMEM_BYTES);

    // 0) tf32 pre-round of GEMM operands
    {
        int nx = (M_ROWS * DMODEL) / 4;
        round_tf32_kernel<<<(nx + 255) / 256, 256>>>(x, pxr, nx);
        int nw1 = (DMODEL * 2 * DINNER) / 4;
        round_tf32_kernel<<<(nw1 + 255) / 256, 256>>>(W_in, pw1, nw1);
        int nw2 = (DINNER * DMODEL) / 4;
        round_tf32_kernel<<<(nw2 + 255) / 256, 256>>>(W_out, pw2, nw2);
    }

    // 1) xz = x @ W_in   (BN=256, 64x64 warp tiles)
    dim3 g1(2 * DINNER / 256, M_ROWS / 128);
    gemm_tf32_pipe<<<g1, 256, PIPE_SMEM_BYTES>>>(pxr, pw1, pxz,
                                                 M_ROWS, 2 * DINNER, DMODEL);

    // 2) proj = silu(conv(xe)) @ W_xproj
    proj_conv_kernel<<<M_ROWS / 32, 256>>>(W_xproj, conv_w, conv_b);

    // 3) chunked scan
    scan_pass1<<<BATCH * NHEADS * NCHUNK, 128>>>(W_dt, b_dt, A_log, conv_w, conv_b);
    scan_pass2<<<(BATCH * NHEADS * HDIM * DSTATE) / 256, 256>>>();
    scan_pass3<<<BATCH * NHEADS * NCHUNK, 128>>>(W_dt, b_dt, A_log, D_skip, conv_w, conv_b);

    // 4) LN stats + apply + tf32 round -> g_yn
    ln_apply_kernel<<<M_ROWS, 256>>>(ln_g, ln_b);

    // 5) out = LN(y) @ W_out
    dim3 g2(DMODEL / 256, M_ROWS / 128);
    gemm_tf32_pipe<<<g2, 256, PIPE_SMEM_BYTES>>>(pyn, pw2, out,
                                                 M_ROWS, DMODEL, DINNER);
}

// round 14
// speedup vs baseline: 1.0919x; 1.0919x over previous
#include <cuda_runtime.h>
#include <math.h>
#include <stdint.h>

// ---------------------------------------------------------------------------
// Problem constants
// ---------------------------------------------------------------------------
#define BATCH   2
#define SEQ     4096
#define DMODEL  1024
#define DINNER  2048
#define NHEADS  16
#define HDIM    128
#define DSTATE  16
#define DCONV   4
#define CHUNK   64
#define NCHUNK  (SEQ / CHUNK)      // 64
#define M_ROWS  (BATCH * SEQ)      // 8192
#define NPROJ   (NHEADS + 2*DSTATE) // 48
#define ROWW    (2 * DINNER)        // g_xz row width
#define LN_EPS  1e-5f

// Pipelined GEMM config (R11 measured-good): BM=128, BN=128, BK=16, 8 warps 64x32
#define PSTAGES    4
#define AS_STRIDE  20                 // padded row pitch (floats)
#define BS_STRIDE  136                // padded row pitch (floats)
#define AS_STAGE   (128 * AS_STRIDE)  // 2560 floats
#define BS_STAGE   (16 * BS_STRIDE)   // 2176 floats
#define PIPE_SMEM_BYTES ((PSTAGES * (AS_STAGE + BS_STAGE)) * 4)  // 75776 B

// ---------------------------------------------------------------------------
// Scratch (static device globals -- no allocation allowed)
// ---------------------------------------------------------------------------
__device__ float  g_xz[(size_t)M_ROWS * ROWW];          // [xe | z]
__device__ float  g_proj[(size_t)M_ROWS * NPROJ];       // dt_raw | B | C
__device__ float  g_y[(size_t)M_ROWS * DINNER];         // raw gated y (pre-LN)
__device__ float  g_yn[(size_t)M_ROWS * DINNER];        // tf32-rounded LN(y)
__device__ float  g_S[(size_t)BATCH*NHEADS*NCHUNK*HDIM*DSTATE];   // chunk-local states
__device__ float  g_Sin[(size_t)BATCH*NHEADS*NCHUNK*HDIM*DSTATE]; // incoming states
__device__ float  g_P[(size_t)BATCH*NHEADS*NCHUNK*HDIM];
__device__ float  g_xr [(size_t)M_ROWS * DMODEL];       // tf32-rounded x
__device__ float  g_w1r[(size_t)DMODEL * 2 * DINNER];   // tf32-rounded W_in
__device__ float  g_w2r[(size_t)DINNER * DMODEL];       // tf32-rounded W_out

// ---------------------------------------------------------------------------
// Helpers
// ---------------------------------------------------------------------------
__device__ __forceinline__ uint32_t tf32_rn(float x) {
    uint32_t r;
    asm("cvt.rna.tf32.f32 %0, %1;" : "=r"(r) : "f"(x));
    return r;
}
__device__ __forceinline__ float4 round4(float4 v) {
    v.x = __uint_as_float(tf32_rn(v.x));
    v.y = __uint_as_float(tf32_rn(v.y));
    v.z = __uint_as_float(tf32_rn(v.z));
    v.w = __uint_as_float(tf32_rn(v.w));
    return v;
}
__device__ __forceinline__ void mma_tf32(float* c, const uint32_t* a, const uint32_t* b) {
    asm volatile(
        "mma.sync.aligned.m16n8k8.row.col.f32.tf32.tf32.f32 "
        "{%0,%1,%2,%3},{%4,%5,%6,%7},{%8,%9},{%0,%1,%2,%3};"
        : "+f"(c[0]), "+f"(c[1]), "+f"(c[2]), "+f"(c[3])
        : "r"(a[0]), "r"(a[1]), "r"(a[2]), "r"(a[3]), "r"(b[0]), "r"(b[1]));
}
// Fast transcendentals in scan/proj: R3-vs-R4 controlled diff showed their
// contribution to final rel_err is ~3e-8 (tf32 GEMM floor 5.24e-4 dominates).
__device__ __forceinline__ float softplus_f(float x) {
    return (x > 20.f) ? x : __logf(1.f + __expf(x));
}
__device__ __forceinline__ float silu_f(float v) {
    return v * __frcp_rn(1.f + __expf(-v));
}
__device__ __forceinline__ float4 ln_apply(float4 v, float mu, float rs,
                                           const float* __restrict__ g,
                                           const float* __restrict__ b, int col) {
    float4 gg = *(const float4*)(g + col);
    float4 bb = *(const float4*)(b + col);
    v.x = (v.x - mu) * rs * gg.x + bb.x;
    v.y = (v.y - mu) * rs * gg.y + bb.y;
    v.z = (v.z - mu) * rs * gg.z + bb.z;
    v.w = (v.w - mu) * rs * gg.w + bb.w;
    return v;
}
__device__ __forceinline__ void cp_async16(const void* smem_dst, const void* gmem_src) {
    uint32_t sa = (uint32_t)__cvta_generic_to_shared(smem_dst);
    asm volatile("cp.async.cg.shared.global [%0], [%1], 16;"
                 :: "r"(sa), "l"(gmem_src) : "memory");
}
#define CP_COMMIT()  asm volatile("cp.async.commit_group;" ::: "memory")
#define CP_WAIT2()   asm volatile("cp.async.wait_group 2;" ::: "memory")

// ---------------------------------------------------------------------------
// Elementwise tf32 pre-round: dst = round_tf32(src). n multiple of 4.
// ---------------------------------------------------------------------------
__global__ __launch_bounds__(256) void round_tf32_kernel(
    const float* __restrict__ src, float* __restrict__ dst, int n4)
{
    int i = blockIdx.x * 256 + threadIdx.x;
    if (i < n4)
        *(float4*)(dst + 4 * (size_t)i) = round4(*(const float4*)(src + 4 * (size_t)i));
}

// ---------------------------------------------------------------------------
// Pipelined TF32 GEMM, cvt-free (operands pre-rounded), R11 configuration.
// C[M,N] = A[M,K] @ B[K,N], 256 threads, BM=BN=128, BK=16, warp tile 64x32.
// ---------------------------------------------------------------------------
__global__ __launch_bounds__(256, 2) void gemm_tf32_pipe(
    const float* __restrict__ A, const float* __restrict__ B,
    float* __restrict__ C, int M, int N, int K)
{
    extern __shared__ __align__(16) float smem[];
    float* As = smem;                          // [PSTAGES][128][AS_STRIDE]
    float* Bs = smem + PSTAGES * AS_STAGE;     // [PSTAGES][16][BS_STRIDE]

    const int tid  = threadIdx.x;
    const int warp = tid >> 5, lane = tid & 31;
    const int g    = lane >> 2, q = lane & 3;
    const int wm   = (warp & 1) * 64;
    const int wn   = (warp >> 1) * 32;
    const int m0   = blockIdx.y * 128;
    const int n0   = blockIdx.x * 128;

    const int ar = tid >> 1;            // A row 0..127
    const int ac = (tid & 1) * 8;       // A col 0 or 8
    const int br = tid >> 4;            // B row 0..15
    const int bc = (tid & 15) * 8;      // B col 0..120

    const float* Abase = A + (size_t)(m0 + ar) * K + ac;
    const float* Bbase = B + (size_t)br * N + n0 + bc;

    const int nk = K >> 4;

    // prefill stages 0..2
#pragma unroll
    for (int s = 0; s < PSTAGES - 1; s++) {
        if (s < nk) {
            const float* Ap = Abase + s * 16;
            const float* Bp = Bbase + (size_t)s * 16 * N;
            float* Ad = As + s * AS_STAGE + ar * AS_STRIDE + ac;
            float* Bd = Bs + s * BS_STAGE + br * BS_STRIDE + bc;
            cp_async16(Ad,     Ap);
            cp_async16(Ad + 4, Ap + 4);
            cp_async16(Bd,     Bp);
            cp_async16(Bd + 4, Bp + 4);
        }
        CP_COMMIT();
    }

    float acc[4][4][4];
#pragma unroll
    for (int i = 0; i < 4; i++)
#pragma unroll
        for (int j = 0; j < 4; j++)
#pragma unroll
            for (int k = 0; k < 4; k++) acc[i][j][k] = 0.f;

    for (int kt = 0; kt < nk; kt++) {
        CP_WAIT2();
        __syncthreads();

        {
            const int kf = kt + PSTAGES - 1;
            if (kf < nk) {
                const int s = kf & (PSTAGES - 1);
                const float* Ap = Abase + kf * 16;
                const float* Bp = Bbase + (size_t)kf * 16 * N;
                float* Ad = As + s * AS_STAGE + ar * AS_STRIDE + ac;
                float* Bd = Bs + s * BS_STAGE + br * BS_STRIDE + bc;
                cp_async16(Ad,     Ap);
                cp_async16(Ad + 4, Ap + 4);
                cp_async16(Bd,     Bp);
                cp_async16(Bd + 4, Bp + 4);
            }
            CP_COMMIT();
        }

        const float* Ac = As + (kt & (PSTAGES - 1)) * AS_STAGE;
        const float* Bc = Bs + (kt & (PSTAGES - 1)) * BS_STAGE;

#pragma unroll
        for (int ks = 0; ks < 2; ks++) {
            uint32_t af[4][4], bf[4][2];
            const int kk = ks * 8 + q;
#pragma unroll
            for (int tm = 0; tm < 4; tm++) {
                const int r = wm + tm * 16 + g;
                af[tm][0] = __float_as_uint(Ac[r * AS_STRIDE + kk]);
                af[tm][1] = __float_as_uint(Ac[(r + 8) * AS_STRIDE + kk]);
                af[tm][2] = __float_as_uint(Ac[r * AS_STRIDE + kk + 4]);
                af[tm][3] = __float_as_uint(Ac[(r + 8) * AS_STRIDE + kk + 4]);
            }
#pragma unroll
            for (int tn = 0; tn < 4; tn++) {
                const int n = wn + tn * 8 + g;
                bf[tn][0] = __float_as_uint(Bc[kk * BS_STRIDE + n]);
                bf[tn][1] = __float_as_uint(Bc[(kk + 4) * BS_STRIDE + n]);
            }
#pragma unroll
            for (int tm = 0; tm < 4; tm++)
#pragma unroll
                for (int tn = 0; tn < 4; tn++)
                    mma_tf32(acc[tm][tn], af[tm], bf[tn]);
        }
    }

#pragma unroll
    for (int tm = 0; tm < 4; tm++) {
        const int row = m0 + wm + tm * 16 + g;
#pragma unroll
        for (int tn = 0; tn < 4; tn++) {
            const int col = n0 + wn + tn * 8 + 2 * q;
            *(float2*)&C[(size_t)row * N + col] =
                make_float2(acc[tm][tn][0], acc[tm][tn][1]);
            *(float2*)&C[(size_t)(row + 8) * N + col] =
                make_float2(acc[tm][tn][2], acc[tm][tn][3]);
        }
    }
}

// ---------------------------------------------------------------------------
// proj + fused depthwise conv + silu.
// ---------------------------------------------------------------------------
__global__ __launch_bounds__(256) void proj_conv_kernel(
    const float* __restrict__ W_xproj, const float* __restrict__ conv_w,
    const float* __restrict__ conv_b)
{
    __shared__ float xr[35][64];
    __shared__ float ws[64][NPROJ];
    __shared__ float xs[32][64];
    const int tid = threadIdx.x;
    const int m0  = blockIdx.x * 32;
    const bool seqstart = ((m0 & (SEQ - 1)) == 0);

    float acc[6];
#pragma unroll
    for (int o = 0; o < 6; o++) acc[o] = 0.f;

    for (int k0 = 0; k0 < DINNER; k0 += 64) {
        for (int t = tid; t < 35 * 64; t += 256) {
            int rr = t >> 6, cc = t & 63;
            float v = 0.f;
            if (!(seqstart && rr < 3))
                v = g_xz[(size_t)(m0 - 3 + rr) * ROWW + k0 + cc];
            xr[rr][cc] = v;
        }
        for (int t = tid; t < 64 * NPROJ; t += 256) {
            int kk = t / NPROJ;
            int j  = t - kk * NPROJ;
            ws[kk][j] = W_xproj[(size_t)(k0 + kk) * NPROJ + j];
        }
        __syncthreads();

        for (int t = tid; t < 32 * 64; t += 256) {
            int r  = t >> 6, cc = t & 63;
            int ch = k0 + cc;
            float4 wv = *(const float4*)(conv_w + (size_t)ch * 4);
            float a = conv_b[ch];
            a = fmaf(wv.x, xr[r][cc],     a);
            a = fmaf(wv.y, xr[r + 1][cc], a);
            a = fmaf(wv.z, xr[r + 2][cc], a);
            a = fmaf(wv.w, xr[r + 3][cc], a);
            xs[r][cc] = silu_f(a);
        }
        __syncthreads();

#pragma unroll
        for (int o = 0; o < 6; o++) {
            int oi = o * 256 + tid;
            int r  = oi / NPROJ;
            int j  = oi - r * NPROJ;
            float a = acc[o];
#pragma unroll 8
            for (int kk = 0; kk < 64; kk++)
                a = fmaf(xs[r][kk], ws[kk][j], a);
            acc[o] = a;
        }
        __syncthreads();
    }
#pragma unroll
    for (int o = 0; o < 6; o++) {
        int oi = o * 256 + tid;
        int r  = oi / NPROJ;
        int j  = oi - r * NPROJ;
        g_proj[(size_t)(m0 + r) * NPROJ + j] = acc[o];
    }
}

// ---------------------------------------------------------------------------
// Chunked scan, pass 1: rolling-window conv+silu, dt/decay on the fly.
// g_P is the PRODUCT of all 64 per-step decays.
// ---------------------------------------------------------------------------
__global__ __launch_bounds__(128) void scan_pass1(
    const float* __restrict__ W_dt, const float* __restrict__ b_dt,
    const float* __restrict__ A_log, const float* __restrict__ conv_w,
    const float* __restrict__ conv_b)
{
    const int blk = blockIdx.x;
    const int c   = blk & (NCHUNK - 1);
    const int h   = (blk >> 6) & (NHEADS - 1);
    const int b   = blk >> 10;
    const int d   = threadIdx.x;
    const int i   = h * HDIM + d;

    __shared__ float sB[CHUNK][DSTATE];
    __shared__ float sR[CHUNK][NHEADS];
    for (int t = threadIdx.x; t < CHUNK * DSTATE; t += 128) {
        int tt = t >> 4, n = t & 15;
        size_t pm = (size_t)(b * SEQ + c * CHUNK + tt) * NPROJ;
        sB[tt][n] = g_proj[pm + NHEADS + n];
        sR[tt][n] = g_proj[pm + n];
    }
    __syncthreads();

    float w[NHEADS];
#pragma unroll
    for (int hh = 0; hh < NHEADS; hh++) w[hh] = W_dt[(size_t)hh * DINNER + i];
    const float bd = b_dt[i];
    const float Ah = -__expf(A_log[h]);
    const float4 cw = *(const float4*)(conv_w + (size_t)i * 4);
    const float cb = conv_b[i];

    const int mbase = b * SEQ + c * CHUNK;
    float x3 = 0.f, x2 = 0.f, x1 = 0.f;
    if (c > 0) {
        x3 = g_xz[(size_t)(mbase - 3) * ROWW + i];
        x2 = g_xz[(size_t)(mbase - 2) * ROWW + i];
        x1 = g_xz[(size_t)(mbase - 1) * ROWW + i];
    }

    float s[DSTATE];
#pragma unroll
    for (int n = 0; n < DSTATE; n++) s[n] = 0.f;
    float cum = 0.f;
    float P   = 1.f;

    for (int tt = 0; tt < CHUNK; tt++) {
        float raw = bd;
#pragma unroll
        for (int hh = 0; hh < NHEADS; hh++) raw = fmaf(sR[tt][hh], w[hh], raw);
        float dtv = softplus_f(raw);
        cum += dtv;
        float a = __expf(Ah * cum);
        P *= a;

        float x0 = g_xz[(size_t)(mbase + tt) * ROWW + i];
        float cv = cb;
        cv = fmaf(cw.x, x3, cv);
        cv = fmaf(cw.y, x2, cv);
        cv = fmaf(cw.z, x1, cv);
        cv = fmaf(cw.w, x0, cv);
        float xc = silu_f(cv);
        x3 = x2; x2 = x1; x1 = x0;

        float u = dtv * xc;
#pragma unroll
        for (int n = 0; n < DSTATE; n++)
            s[n] = fmaf(s[n], a, u * sB[tt][n]);
    }
    const int base = ((b * NHEADS + h) * NCHUNK + c) * HDIM + d;
    g_P[base] = P;
#pragma unroll
    for (int n = 0; n < DSTATE; n++) g_S[(size_t)base * DSTATE + n] = s[n];
}

// ---------------------------------------------------------------------------
// Pass 2: stitch across chunks (separate in/out buffers -> pipelined loads).
// ---------------------------------------------------------------------------
__global__ __launch_bounds__(256) void scan_pass2()
{
    const int idx = blockIdx.x * 256 + threadIdx.x;   // BATCH*NHEADS*HDIM*DSTATE
    const int n   = idx & (DSTATE - 1);
    const int d   = (idx >> 4) & (HDIM - 1);
    const int bh  = idx >> 11;                        // 0..31

    float s = 0.f;
#pragma unroll 8
    for (int c = 0; c < NCHUNK; c++) {
        const int base = (bh * NCHUNK + c) * HDIM + d;
        const float Pv = g_P[base];
        const size_t off = (size_t)base * DSTATE + n;
        const float Sl = g_S[off];
        g_Sin[off] = s;               // incoming state for chunk c
        s = fmaf(Pv, s, Sl);
    }
}

// ---------------------------------------------------------------------------
// Pass 3: replay (rolling conv) + y = C.s + D*x, gate with silu(z) -> g_y raw
// ---------------------------------------------------------------------------
__global__ __launch_bounds__(128) void scan_pass3(
    const float* __restrict__ W_dt, const float* __restrict__ b_dt,
    const float* __restrict__ A_log, const float* __restrict__ D_skip,
    const float* __restrict__ conv_w, const float* __restrict__ conv_b)
{
    const int blk = blockIdx.x;
    const int c   = blk & (NCHUNK - 1);
    const int h   = (blk >> 6) & (NHEADS - 1);
    const int b   = blk >> 10;
    const int d   = threadIdx.x;
    const int i   = h * HDIM + d;

    __shared__ float sB[CHUNK][DSTATE];
    __shared__ float sC[CHUNK][DSTATE];
    __shared__ float sR[CHUNK][NHEADS];
    for (int t = threadIdx.x; t < CHUNK * DSTATE; t += 128) {
        int tt = t >> 4, n = t & 15;
        size_t pm = (size_t)(b * SEQ + c * CHUNK + tt) * NPROJ;
        sB[tt][n] = g_proj[pm + NHEADS + n];
        sC[tt][n] = g_proj[pm + NHEADS + DSTATE + n];
        sR[tt][n] = g_proj[pm + n];
    }
    __syncthreads();

    float w[NHEADS];
#pragma unroll
    for (int hh = 0; hh < NHEADS; hh++) w[hh] = W_dt[(size_t)hh * DINNER + i];
    const float bd = b_dt[i];
    const float Ah = -__expf(A_log[h]);
    const float Dh = D_skip[h];
    const float4 cw = *(const float4*)(conv_w + (size_t)i * 4);
    const float cb = conv_b[i];

    const int base = ((b * NHEADS + h) * NCHUNK + c) * HDIM + d;
    float s[DSTATE];
#pragma unroll
    for (int n = 0; n < DSTATE; n++) s[n] = g_Sin[(size_t)base * DSTATE + n];

    const int mbase = b * SEQ + c * CHUNK;
    float x3 = 0.f, x2 = 0.f, x1 = 0.f;
    if (c > 0) {
        x3 = g_xz[(size_t)(mbase - 3) * ROWW + i];
        x2 = g_xz[(size_t)(mbase - 2) * ROWW + i];
        x1 = g_xz[(size_t)(mbase - 1) * ROWW + i];
    }

    float cum = 0.f;
    for (int tt = 0; tt < CHUNK; tt++) {
        float raw = bd;
#pragma unroll
        for (int hh = 0; hh < NHEADS; hh++) raw = fmaf(sR[tt][hh], w[hh], raw);
        float dtv = softplus_f(raw);
        cum += dtv;
        float a = __expf(Ah * cum);

        const size_t rowoff = (size_t)(mbase + tt) * ROWW;
        float x0 = g_xz[rowoff + i];
        float cv = cb;
        cv = fmaf(cw.x, x3, cv);
        cv = fmaf(cw.y, x2, cv);
        cv = fmaf(cw.z, x1, cv);
        cv = fmaf(cw.w, x0, cv);
        float xc = silu_f(cv);
        x3 = x2; x2 = x1; x1 = x0;

        float u = dtv * xc;
        float y = 0.f;
#pragma unroll
        for (int n = 0; n < DSTATE; n++) {
            s[n] = fmaf(s[n], a, u * sB[tt][n]);
            y    = fmaf(s[n], sC[tt][n], y);
        }
        y = fmaf(Dh, xc, y);
        float zv = g_xz[rowoff + DINNER + i];
        y *= silu_f(zv);
        g_y[(size_t)(mbase + tt) * DINNER + i] = y;
    }
}

// ---------------------------------------------------------------------------
// LayerNorm stats + apply + tf32 round: g_y -> g_yn (ready for cvt-free GEMM2).
// ---------------------------------------------------------------------------
__global__ __launch_bounds__(256) void ln_apply_kernel(
    const float* __restrict__ ln_g, const float* __restrict__ ln_b)
{
    __shared__ float sh[8];
    __shared__ float s_mu, s_rstd;
    const int m   = blockIdx.x;
    const int tid = threadIdx.x;
    const float* row = g_y + (size_t)m * DINNER;
    float* rown = g_yn + (size_t)m * DINNER;

    const int i0 = tid * 4;
    float4 a  = *(const float4*)(row + i0);
    float4 b4 = *(const float4*)(row + 1024 + i0);
    float v[8] = {a.x, a.y, a.z, a.w, b4.x, b4.y, b4.z, b4.w};

    float sum = 0.f;
#pragma unroll
    for (int k = 0; k < 8; k++) sum += v[k];
#pragma unroll
    for (int o = 16; o > 0; o >>= 1) sum += __shfl_xor_sync(0xffffffffu, sum, o);
    if ((tid & 31) == 0) sh[tid >> 5] = sum;
    __syncthreads();
    if (tid < 32) {
        float t = (tid < 8) ? sh[tid] : 0.f;
#pragma unroll
        for (int o = 4; o > 0; o >>= 1) t += __shfl_xor_sync(0xffffffffu, t, o);
        if (tid == 0) s_mu = t * (1.f / (float)DINNER);
    }
    __syncthreads();
    const float mu = s_mu;

    float var = 0.f;
#pragma unroll
    for (int k = 0; k < 8; k++) { float dv = v[k] - mu; var = fmaf(dv, dv, var); }
#pragma unroll
    for (int o = 16; o > 0; o >>= 1) var += __shfl_xor_sync(0xffffffffu, var, o);
    __syncthreads();
    if ((tid & 31) == 0) sh[tid >> 5] = var;
    __syncthreads();
    if (tid < 32) {
        float t = (tid < 8) ? sh[tid] : 0.f;
#pragma unroll
        for (int o = 4; o > 0; o >>= 1) t += __shfl_xor_sync(0xffffffffu, t, o);
        if (tid == 0) s_rstd = rsqrtf(t * (1.f / (float)DINNER) + LN_EPS);
    }
    __syncthreads();
    const float rs = s_rstd;

    float4 lo = make_float4(v[0], v[1], v[2], v[3]);
    float4 hi = make_float4(v[4], v[5], v[6], v[7]);
    *(float4*)(rown + i0)        = round4(ln_apply(lo, mu, rs, ln_g, ln_b, i0));
    *(float4*)(rown + 1024 + i0) = round4(ln_apply(hi, mu, rs, ln_g, ln_b, 1024 + i0));
}

// ---------------------------------------------------------------------------
// kernel_launch
// ---------------------------------------------------------------------------
extern "C" void kernel_launch(void* const* d_in, const int* in_sizes, int n_in,
                              void* d_out, int out_size)
{
    const float* x       = (const float*)d_in[0];
    const float* W_in    = (const float*)d_in[1];
    const float* conv_w  = (const float*)d_in[2];
    const float* conv_b  = (const float*)d_in[3];
    const float* W_xproj = (const float*)d_in[4];
    const float* W_dt    = (const float*)d_in[5];
    const float* b_dt    = (const float*)d_in[6];
    const float* A_log   = (const float*)d_in[7];
    const float* D_skip  = (const float*)d_in[8];
    const float* W_out   = (const float*)d_in[9];
    const float* ln_g    = (const float*)d_in[10];
    const float* ln_b    = (const float*)d_in[11];
    float* out = (float*)d_out;

    float *pxz = nullptr, *pxr = nullptr, *pw1 = nullptr, *pw2 = nullptr, *pyn = nullptr;
    cudaGetSymbolAddress((void**)&pxz, g_xz);
    cudaGetSymbolAddress((void**)&pxr, g_xr);
    cudaGetSymbolAddress((void**)&pw1, g_w1r);
    cudaGetSymbolAddress((void**)&pw2, g_w2r);
    cudaGetSymbolAddress((void**)&pyn, g_yn);

    cudaFuncSetAttribute(gemm_tf32_pipe,
                         cudaFuncAttributeMaxDynamicSharedMemorySize,
                         PIPE_SMEM_BYTES);

    // 0) tf32 pre-round of GEMM operands
    {
        int nx = (M_ROWS * DMODEL) / 4;
        round_tf32_kernel<<<(nx + 255) / 256, 256>>>(x, pxr, nx);
        int nw1 = (DMODEL * 2 * DINNER) / 4;
        round_tf32_kernel<<<(nw1 + 255) / 256, 256>>>(W_in, pw1, nw1);
        int nw2 = (DINNER * DMODEL) / 4;
        round_tf32_kernel<<<(nw2 + 255) / 256, 256>>>(W_out, pw2, nw2);
    }

    // 1) xz = x @ W_in   (BN=128 R11 config)
    dim3 g1(2 * DINNER / 128, M_ROWS / 128);
    gemm_tf32_pipe<<<g1, 256, PIPE_SMEM_BYTES>>>(pxr, pw1, pxz,
                                                 M_ROWS, 2 * DINNER, DMODEL);

    // 2) proj = silu(conv(xe)) @ W_xproj
    proj_conv_kernel<<<M_ROWS / 32, 256>>>(W_xproj, conv_w, conv_b);

    // 3) chunked scan
    scan_pass1<<<BATCH * NHEADS * NCHUNK, 128>>>(W_dt, b_dt, A_log, conv_w, conv_b);
    scan_pass2<<<(BATCH * NHEADS * HDIM * DSTATE) / 256, 256>>>();
    scan_pass3<<<BATCH * NHEADS * NCHUNK, 128>>>(W_dt, b_dt, A_log, D_skip, conv_w, conv_b);

    // 4) LN stats + apply + tf32 round -> g_yn
    ln_apply_kernel<<<M_ROWS, 256>>>(ln_g, ln_b);

    // 5) out = LN(y) @ W_out
    dim3 g2(DMODEL / 128, M_ROWS / 128);
    gemm_tf32_pipe<<<g2, 256, PIPE_SMEM_BYTES>>>(pyn, pw2, out,
                                                 M_ROWS, DMODEL, DINNER);
}

// round 15
// speedup vs baseline: 1.5847x; 1.4513x over previous
#include <cuda_runtime.h>
#include <cuda_fp16.h>
#include <math.h>
#include <stdint.h>

// ---------------------------------------------------------------------------
// Problem constants
// ---------------------------------------------------------------------------
#define BATCH   2
#define SEQ     4096
#define DMODEL  1024
#define DINNER  2048
#define NHEADS  16
#define HDIM    128
#define DSTATE  16
#define DCONV   4
#define CHUNK   64
#define NCHUNK  (SEQ / CHUNK)      // 64
#define M_ROWS  (BATCH * SEQ)      // 8192
#define NPROJ   (NHEADS + 2*DSTATE) // 48
#define ROWW    (2 * DINNER)        // g_xz row width
#define LN_EPS  1e-5f

// fp16 pipelined GEMM config: BM=BN=128, BK=16, 8 warps of 64x32, 4 stages
#define PSTAGES    4
#define ASW        12                 // A row pitch in 32-bit words (= 24 halves)
#define BSW        136                // B row pitch in half2 words (128 + 8 pad)
#define A_STAGE_W  (128 * ASW)        // 1536 words
#define B_STAGE_W  (8 * BSW)          // 1088 words
#define PIPE_SMEM_BYTES ((PSTAGES * (A_STAGE_W + B_STAGE_W)) * 4)  // 41984 B

// ---------------------------------------------------------------------------
// Scratch (static device globals -- no allocation allowed)
// ---------------------------------------------------------------------------
__device__ float  g_xz[(size_t)M_ROWS * ROWW];          // [xe | z]
__device__ float  g_proj[(size_t)M_ROWS * NPROJ];       // dt_raw | B | C
__device__ float  g_y[(size_t)M_ROWS * DINNER];         // raw gated y (pre-LN)
__device__ float  g_S[(size_t)BATCH*NHEADS*NCHUNK*HDIM*DSTATE];
__device__ float  g_Sin[(size_t)BATCH*NHEADS*NCHUNK*HDIM*DSTATE];
__device__ float  g_P[(size_t)BATCH*NHEADS*NCHUNK*HDIM];
__device__ __align__(16) __half  g_xh [(size_t)M_ROWS * DMODEL];       // fp16 x
__device__ __align__(16) __half2 g_w1h[(size_t)(DMODEL/2) * 2*DINNER]; // packed W_in
__device__ __align__(16) __half2 g_w2h[(size_t)(DINNER/2) * DMODEL];   // packed W_out
__device__ __align__(16) __half  g_ynh[(size_t)M_ROWS * DINNER];       // fp16 LN(y)

// ---------------------------------------------------------------------------
// Helpers
// ---------------------------------------------------------------------------
__device__ __forceinline__ void mma_f16(float* c, const uint32_t* a, const uint32_t* b) {
    asm volatile(
        "mma.sync.aligned.m16n8k16.row.col.f32.f16.f16.f32 "
        "{%0,%1,%2,%3},{%4,%5,%6,%7},{%8,%9},{%0,%1,%2,%3};"
        : "+f"(c[0]), "+f"(c[1]), "+f"(c[2]), "+f"(c[3])
        : "r"(a[0]), "r"(a[1]), "r"(a[2]), "r"(a[3]), "r"(b[0]), "r"(b[1]));
}
__device__ __forceinline__ float softplus_f(float x) {
    return (x > 20.f) ? x : __logf(1.f + __expf(x));
}
__device__ __forceinline__ float silu_f(float v) {
    return v * __frcp_rn(1.f + __expf(-v));
}
__device__ __forceinline__ float4 ln_apply(float4 v, float mu, float rs,
                                           const float* __restrict__ g,
                                           const float* __restrict__ b, int col) {
    float4 gg = *(const float4*)(g + col);
    float4 bb = *(const float4*)(b + col);
    v.x = (v.x - mu) * rs * gg.x + bb.x;
    v.y = (v.y - mu) * rs * gg.y + bb.y;
    v.z = (v.z - mu) * rs * gg.z + bb.z;
    v.w = (v.w - mu) * rs * gg.w + bb.w;
    return v;
}
__device__ __forceinline__ uint32_t h2_bits(__half2 h) {
    return *reinterpret_cast<uint32_t*>(&h);
}
__device__ __forceinline__ void cp_async16(const void* smem_dst, const void* gmem_src) {
    uint32_t sa = (uint32_t)__cvta_generic_to_shared(smem_dst);
    asm volatile("cp.async.cg.shared.global [%0], [%1], 16;"
                 :: "r"(sa), "l"(gmem_src) : "memory");
}
#define CP_COMMIT()  asm volatile("cp.async.commit_group;" ::: "memory")
#define CP_WAIT2()   asm volatile("cp.async.wait_group 2;" ::: "memory")

// ---------------------------------------------------------------------------
// fp16 conversions.
// ---------------------------------------------------------------------------
__global__ __launch_bounds__(256) void cvt_a_f16_kernel(
    const float* __restrict__ src, __half* __restrict__ dst, int n4)
{
    int i = blockIdx.x * 256 + threadIdx.x;
    if (i < n4) {
        float4 v = ((const float4*)src)[i];
        __half2 h0 = __floats2half2_rn(v.x, v.y);
        __half2 h1 = __floats2half2_rn(v.z, v.w);
        ((uint2*)dst)[i] = make_uint2(h2_bits(h0), h2_bits(h1));
    }
}
// W [K][N] row-major fp32 -> packed half2 [(K/2)][N]: (W[2kp][n], W[2kp+1][n])
__global__ __launch_bounds__(256) void cvt_w_f16_packed_kernel(
    const float* __restrict__ W, __half2* __restrict__ dst, int Kdim, int Ndim)
{
    int idx = blockIdx.x * 256 + threadIdx.x;
    int nq = Ndim >> 2;
    int total = (Kdim >> 1) * nq;
    if (idx >= total) return;
    int kp = idx / nq;
    int n  = (idx - kp * nq) << 2;
    const float* r0 = W + (size_t)(2 * kp) * Ndim + n;
    const float* r1 = r0 + Ndim;
    float4 a = *(const float4*)r0;
    float4 b = *(const float4*)r1;
    uint4 u;
    u.x = h2_bits(__floats2half2_rn(a.x, b.x));
    u.y = h2_bits(__floats2half2_rn(a.y, b.y));
    u.z = h2_bits(__floats2half2_rn(a.z, b.z));
    u.w = h2_bits(__floats2half2_rn(a.w, b.w));
    *(uint4*)(dst + (size_t)kp * Ndim + n) = u;
}

// ---------------------------------------------------------------------------
// Pipelined FP16 GEMM: C[M,N] = A[M,K] @ B[K,N], fp32 accumulate.
// A: fp16 row-major. B: packed half2 k-pair layout [(K/2)][N].
// 256 threads, BM=BN=128, BK=16, warp tile 64x32, 4-stage cp.async.
// ---------------------------------------------------------------------------
__global__ __launch_bounds__(256, 2) void gemm_f16_pipe(
    const __half* __restrict__ A, const __half2* __restrict__ B,
    float* __restrict__ C, int M, int N, int K)
{
    extern __shared__ __align__(16) uint32_t smemW[];
    uint32_t* As = smemW;                             // [PSTAGES][128][ASW]
    uint32_t* Bs = smemW + PSTAGES * A_STAGE_W;       // [PSTAGES][8][BSW]

    const int tid  = threadIdx.x;
    const int warp = tid >> 5, lane = tid & 31;
    const int g    = lane >> 2, q = lane & 3;
    const int wm   = (warp & 1) * 64;
    const int wn   = (warp >> 1) * 32;
    const int m0   = blockIdx.y * 128;
    const int n0   = blockIdx.x * 128;

    const int ar = tid >> 1;            // A row 0..127
    const int ah = (tid & 1) * 8;       // A col (halves) 0 or 8
    const int br = tid >> 5;            // B kp row 0..7
    const int bn = (tid & 31) * 4;      // B n offset 0..124

    const __half*  Abase = A + (size_t)(m0 + ar) * K + ah;
    const __half2* Bbase = B + (size_t)br * N + n0 + bn;

    const int nk = K >> 4;

    // prefill stages 0..2
#pragma unroll
    for (int s = 0; s < PSTAGES - 1; s++) {
        if (s < nk) {
            const __half*  Ap = Abase + s * 16;
            const __half2* Bp = Bbase + (size_t)s * 8 * N;
            uint32_t* Ad = As + s * A_STAGE_W + ar * ASW + (tid & 1) * 4;
            uint32_t* Bd = Bs + s * B_STAGE_W + br * BSW + bn;
            cp_async16(Ad, Ap);
            cp_async16(Bd, Bp);
        }
        CP_COMMIT();
    }

    float acc[4][4][4];
#pragma unroll
    for (int i = 0; i < 4; i++)
#pragma unroll
        for (int j = 0; j < 4; j++)
#pragma unroll
            for (int k = 0; k < 4; k++) acc[i][j][k] = 0.f;

    for (int kt = 0; kt < nk; kt++) {
        CP_WAIT2();
        __syncthreads();

        {
            const int kf = kt + PSTAGES - 1;
            if (kf < nk) {
                const int s = kf & (PSTAGES - 1);
                const __half*  Ap = Abase + kf * 16;
                const __half2* Bp = Bbase + (size_t)kf * 8 * N;
                uint32_t* Ad = As + s * A_STAGE_W + ar * ASW + (tid & 1) * 4;
                uint32_t* Bd = Bs + s * B_STAGE_W + br * BSW + bn;
                cp_async16(Ad, Ap);
                cp_async16(Bd, Bp);
            }
            CP_COMMIT();
        }

        const uint32_t* Ac = As + (kt & (PSTAGES - 1)) * A_STAGE_W;
        const uint32_t* Bc = Bs + (kt & (PSTAGES - 1)) * B_STAGE_W;

        uint32_t af[4][4], bf[4][2];
#pragma unroll
        for (int tm = 0; tm < 4; tm++) {
            const int r = wm + tm * 16 + g;
            af[tm][0] = Ac[r * ASW + q];
            af[tm][1] = Ac[(r + 8) * ASW + q];
            af[tm][2] = Ac[r * ASW + q + 4];
            af[tm][3] = Ac[(r + 8) * ASW + q + 4];
        }
#pragma unroll
        for (int tn = 0; tn < 4; tn++) {
            const int n = wn + tn * 8 + g;
            bf[tn][0] = Bc[q * BSW + n];
            bf[tn][1] = Bc[(q + 4) * BSW + n];
        }
#pragma unroll
        for (int tm = 0; tm < 4; tm++)
#pragma unroll
            for (int tn = 0; tn < 4; tn++)
                mma_f16(acc[tm][tn], af[tm], bf[tn]);
    }

#pragma unroll
    for (int tm = 0; tm < 4; tm++) {
        const int row = m0 + wm + tm * 16 + g;
#pragma unroll
        for (int tn = 0; tn < 4; tn++) {
            const int col = n0 + wn + tn * 8 + 2 * q;
            *(float2*)&C[(size_t)row * N + col] =
                make_float2(acc[tm][tn][0], acc[tm][tn][1]);
            *(float2*)&C[(size_t)(row + 8) * N + col] =
                make_float2(acc[tm][tn][2], acc[tm][tn][3]);
        }
    }
}

// ---------------------------------------------------------------------------
// proj + fused depthwise conv + silu.
// ---------------------------------------------------------------------------
__global__ __launch_bounds__(256) void proj_conv_kernel(
    const float* __restrict__ W_xproj, const float* __restrict__ conv_w,
    const float* __restrict__ conv_b)
{
    __shared__ float xr[35][64];
    __shared__ float ws[64][NPROJ];
    __shared__ float xs[32][64];
    const int tid = threadIdx.x;
    const int m0  = blockIdx.x * 32;
    const bool seqstart = ((m0 & (SEQ - 1)) == 0);

    float acc[6];
#pragma unroll
    for (int o = 0; o < 6; o++) acc[o] = 0.f;

    for (int k0 = 0; k0 < DINNER; k0 += 64) {
        for (int t = tid; t < 35 * 64; t += 256) {
            int rr = t >> 6, cc = t & 63;
            float v = 0.f;
            if (!(seqstart && rr < 3))
                v = g_xz[(size_t)(m0 - 3 + rr) * ROWW + k0 + cc];
            xr[rr][cc] = v;
        }
        for (int t = tid; t < 64 * NPROJ; t += 256) {
            int kk = t / NPROJ;
            int j  = t - kk * NPROJ;
            ws[kk][j] = W_xproj[(size_t)(k0 + kk) * NPROJ + j];
        }
        __syncthreads();

        for (int t = tid; t < 32 * 64; t += 256) {
            int r  = t >> 6, cc = t & 63;
            int ch = k0 + cc;
            float4 wv = *(const float4*)(conv_w + (size_t)ch * 4);
            float a = conv_b[ch];
            a = fmaf(wv.x, xr[r][cc],     a);
            a = fmaf(wv.y, xr[r + 1][cc], a);
            a = fmaf(wv.z, xr[r + 2][cc], a);
            a = fmaf(wv.w, xr[r + 3][cc], a);
            xs[r][cc] = silu_f(a);
        }
        __syncthreads();

#pragma unroll
        for (int o = 0; o < 6; o++) {
            int oi = o * 256 + tid;
            int r  = oi / NPROJ;
            int j  = oi - r * NPROJ;
            float a = acc[o];
#pragma unroll 8
            for (int kk = 0; kk < 64; kk++)
                a = fmaf(xs[r][kk], ws[kk][j], a);
            acc[o] = a;
        }
        __syncthreads();
    }
#pragma unroll
    for (int o = 0; o < 6; o++) {
        int oi = o * 256 + tid;
        int r  = oi / NPROJ;
        int j  = oi - r * NPROJ;
        g_proj[(size_t)(m0 + r) * NPROJ + j] = acc[o];
    }
}

// ---------------------------------------------------------------------------
// Chunked scan, pass 1: rolling-window conv+silu, dt/decay on the fly.
// g_P is the PRODUCT of all 64 per-step decays.
// ---------------------------------------------------------------------------
__global__ __launch_bounds__(128) void scan_pass1(
    const float* __restrict__ W_dt, const float* __restrict__ b_dt,
    const float* __restrict__ A_log, const float* __restrict__ conv_w,
    const float* __restrict__ conv_b)
{
    const int blk = blockIdx.x;
    const int c   = blk & (NCHUNK - 1);
    const int h   = (blk >> 6) & (NHEADS - 1);
    const int b   = blk >> 10;
    const int d   = threadIdx.x;
    const int i   = h * HDIM + d;

    __shared__ float sB[CHUNK][DSTATE];
    __shared__ float sR[CHUNK][NHEADS];
    for (int t = threadIdx.x; t < CHUNK * DSTATE; t += 128) {
        int tt = t >> 4, n = t & 15;
        size_t pm = (size_t)(b * SEQ + c * CHUNK + tt) * NPROJ;
        sB[tt][n] = g_proj[pm + NHEADS + n];
        sR[tt][n] = g_proj[pm + n];
    }
    __syncthreads();

    float w[NHEADS];
#pragma unroll
    for (int hh = 0; hh < NHEADS; hh++) w[hh] = W_dt[(size_t)hh * DINNER + i];
    const float bd = b_dt[i];
    const float Ah = -__expf(A_log[h]);
    const float4 cw = *(const float4*)(conv_w + (size_t)i * 4);
    const float cb = conv_b[i];

    const int mbase = b * SEQ + c * CHUNK;
    float x3 = 0.f, x2 = 0.f, x1 = 0.f;
    if (c > 0) {
        x3 = g_xz[(size_t)(mbase - 3) * ROWW + i];
        x2 = g_xz[(size_t)(mbase - 2) * ROWW + i];
        x1 = g_xz[(size_t)(mbase - 1) * ROWW + i];
    }

    float s[DSTATE];
#pragma unroll
    for (int n = 0; n < DSTATE; n++) s[n] = 0.f;
    float cum = 0.f;
    float P   = 1.f;

    for (int tt = 0; tt < CHUNK; tt++) {
        float raw = bd;
#pragma unroll
        for (int hh = 0; hh < NHEADS; hh++) raw = fmaf(sR[tt][hh], w[hh], raw);
        float dtv = softplus_f(raw);
        cum += dtv;
        float a = __expf(Ah * cum);
        P *= a;

        float x0 = g_xz[(size_t)(mbase + tt) * ROWW + i];
        float cv = cb;
        cv = fmaf(cw.x, x3, cv);
        cv = fmaf(cw.y, x2, cv);
        cv = fmaf(cw.z, x1, cv);
        cv = fmaf(cw.w, x0, cv);
        float xc = silu_f(cv);
        x3 = x2; x2 = x1; x1 = x0;

        float u = dtv * xc;
#pragma unroll
        for (int n = 0; n < DSTATE; n++)
            s[n] = fmaf(s[n], a, u * sB[tt][n]);
    }
    const int base = ((b * NHEADS + h) * NCHUNK + c) * HDIM + d;
    g_P[base] = P;
#pragma unroll
    for (int n = 0; n < DSTATE; n++) g_S[(size_t)base * DSTATE + n] = s[n];
}

// ---------------------------------------------------------------------------
// Pass 2: stitch across chunks (separate in/out buffers -> pipelined loads).
// ---------------------------------------------------------------------------
__global__ __launch_bounds__(256) void scan_pass2()
{
    const int idx = blockIdx.x * 256 + threadIdx.x;
    const int n   = idx & (DSTATE - 1);
    const int d   = (idx >> 4) & (HDIM - 1);
    const int bh  = idx >> 11;

    float s = 0.f;
#pragma unroll 8
    for (int c = 0; c < NCHUNK; c++) {
        const int base = (bh * NCHUNK + c) * HDIM + d;
        const float Pv = g_P[base];
        const size_t off = (size_t)base * DSTATE + n;
        const float Sl = g_S[off];
        g_Sin[off] = s;
        s = fmaf(Pv, s, Sl);
    }
}

// ---------------------------------------------------------------------------
// Pass 3: replay (rolling conv) + y = C.s + D*x, gate with silu(z) -> g_y raw
// ---------------------------------------------------------------------------
__global__ __launch_bounds__(128) void scan_pass3(
    const float* __restrict__ W_dt, const float* __restrict__ b_dt,
    const float* __restrict__ A_log, const float* __restrict__ D_skip,
    const float* __restrict__ conv_w, const float* __restrict__ conv_b)
{
    const int blk = blockIdx.x;
    const int c   = blk & (NCHUNK - 1);
    const int h   = (blk >> 6) & (NHEADS - 1);
    const int b   = blk >> 10;
    const int d   = threadIdx.x;
    const int i   = h * HDIM + d;

    __shared__ float sB[CHUNK][DSTATE];
    __shared__ float sC[CHUNK][DSTATE];
    __shared__ float sR[CHUNK][NHEADS];
    for (int t = threadIdx.x; t < CHUNK * DSTATE; t += 128) {
        int tt = t >> 4, n = t & 15;
        size_t pm = (size_t)(b * SEQ + c * CHUNK + tt) * NPROJ;
        sB[tt][n] = g_proj[pm + NHEADS + n];
        sC[tt][n] = g_proj[pm + NHEADS + DSTATE + n];
        sR[tt][n] = g_proj[pm + n];
    }
    __syncthreads();

    float w[NHEADS];
#pragma unroll
    for (int hh = 0; hh < NHEADS; hh++) w[hh] = W_dt[(size_t)hh * DINNER + i];
    const float bd = b_dt[i];
    const float Ah = -__expf(A_log[h]);
    const float Dh = D_skip[h];
    const float4 cw = *(const float4*)(conv_w + (size_t)i * 4);
    const float cb = conv_b[i];

    const int base = ((b * NHEADS + h) * NCHUNK + c) * HDIM + d;
    float s[DSTATE];
#pragma unroll
    for (int n = 0; n < DSTATE; n++) s[n] = g_Sin[(size_t)base * DSTATE + n];

    const int mbase = b * SEQ + c * CHUNK;
    float x3 = 0.f, x2 = 0.f, x1 = 0.f;
    if (c > 0) {
        x3 = g_xz[(size_t)(mbase - 3) * ROWW + i];
        x2 = g_xz[(size_t)(mbase - 2) * ROWW + i];
        x1 = g_xz[(size_t)(mbase - 1) * ROWW + i];
    }

    float cum = 0.f;
    for (int tt = 0; tt < CHUNK; tt++) {
        float raw = bd;
#pragma unroll
        for (int hh = 0; hh < NHEADS; hh++) raw = fmaf(sR[tt][hh], w[hh], raw);
        float dtv = softplus_f(raw);
        cum += dtv;
        float a = __expf(Ah * cum);

        const size_t rowoff = (size_t)(mbase + tt) * ROWW;
        float x0 = g_xz[rowoff + i];
        float cv = cb;
        cv = fmaf(cw.x, x3, cv);
        cv = fmaf(cw.y, x2, cv);
        cv = fmaf(cw.z, x1, cv);
        cv = fmaf(cw.w, x0, cv);
        float xc = silu_f(cv);
        x3 = x2; x2 = x1; x1 = x0;

        float u = dtv * xc;
        float y = 0.f;
#pragma unroll
        for (int n = 0; n < DSTATE; n++) {
            s[n] = fmaf(s[n], a, u * sB[tt][n]);
            y    = fmaf(s[n], sC[tt][n], y);
        }
        y = fmaf(Dh, xc, y);
        float zv = g_xz[rowoff + DINNER + i];
        y *= silu_f(zv);
        g_y[(size_t)(mbase + tt) * DINNER + i] = y;
    }
}

// ---------------------------------------------------------------------------
// LayerNorm stats + apply + fp16 convert: g_y -> g_ynh (A operand of GEMM2).
// ---------------------------------------------------------------------------
__global__ __launch_bounds__(256) void ln_apply_kernel(
    const float* __restrict__ ln_g, const float* __restrict__ ln_b)
{
    __shared__ float sh[8];
    __shared__ float s_mu, s_rstd;
    const int m   = blockIdx.x;
    const int tid = threadIdx.x;
    const float* row = g_y + (size_t)m * DINNER;
    __half* rown = g_ynh + (size_t)m * DINNER;

    const int i0 = tid * 4;
    float4 a  = *(const float4*)(row + i0);
    float4 b4 = *(const float4*)(row + 1024 + i0);
    float v[8] = {a.x, a.y, a.z, a.w, b4.x, b4.y, b4.z, b4.w};

    float sum = 0.f;
#pragma unroll
    for (int k = 0; k < 8; k++) sum += v[k];
#pragma unroll
    for (int o = 16; o > 0; o >>= 1) sum += __shfl_xor_sync(0xffffffffu, sum, o);
    if ((tid & 31) == 0) sh[tid >> 5] = sum;
    __syncthreads();
    if (tid < 32) {
        float t = (tid < 8) ? sh[tid] : 0.f;
#pragma unroll
        for (int o = 4; o > 0; o >>= 1) t += __shfl_xor_sync(0xffffffffu, t, o);
        if (tid == 0) s_mu = t * (1.f / (float)DINNER);
    }
    __syncthreads();
    const float mu = s_mu;

    float var = 0.f;
#pragma unroll
    for (int k = 0; k < 8; k++) { float dv = v[k] - mu; var = fmaf(dv, dv, var); }
#pragma unroll
    for (int o = 16; o > 0; o >>= 1) var += __shfl_xor_sync(0xffffffffu, var, o);
    __syncthreads();
    if ((tid & 31) == 0) sh[tid >> 5] = var;
    __syncthreads();
    if (tid < 32) {
        float t = (tid < 8) ? sh[tid] : 0.f;
#pragma unroll
        for (int o = 4; o > 0; o >>= 1) t += __shfl_xor_sync(0xffffffffu, t, o);
        if (tid == 0) s_rstd = rsqrtf(t * (1.f / (float)DINNER) + LN_EPS);
    }
    __syncthreads();
    const float rs = s_rstd;

    float4 lo = ln_apply(make_float4(v[0], v[1], v[2], v[3]), mu, rs, ln_g, ln_b, i0);
    float4 hi = ln_apply(make_float4(v[4], v[5], v[6], v[7]), mu, rs, ln_g, ln_b, 1024 + i0);
    *(uint2*)(rown + i0) = make_uint2(
        h2_bits(__floats2half2_rn(lo.x, lo.y)), h2_bits(__floats2half2_rn(lo.z, lo.w)));
    *(uint2*)(rown + 1024 + i0) = make_uint2(
        h2_bits(__floats2half2_rn(hi.x, hi.y)), h2_bits(__floats2half2_rn(hi.z, hi.w)));
}

// ---------------------------------------------------------------------------
// kernel_launch
// ---------------------------------------------------------------------------
extern "C" void kernel_launch(void* const* d_in, const int* in_sizes, int n_in,
                              void* d_out, int out_size)
{
    const float* x       = (const float*)d_in[0];
    const float* W_in    = (const float*)d_in[1];
    const float* conv_w  = (const float*)d_in[2];
    const float* conv_b  = (const float*)d_in[3];
    const float* W_xproj = (const float*)d_in[4];
    const float* W_dt    = (const float*)d_in[5];
    const float* b_dt    = (const float*)d_in[6];
    const float* A_log   = (const float*)d_in[7];
    const float* D_skip  = (const float*)d_in[8];
    const float* W_out   = (const float*)d_in[9];
    const float* ln_g    = (const float*)d_in[10];
    const float* ln_b    = (const float*)d_in[11];
    float* out = (float*)d_out;

    float  *pxz = nullptr;
    __half *pxh = nullptr, *pyh = nullptr;
    __half2 *pw1 = nullptr, *pw2 = nullptr;
    cudaGetSymbolAddress((void**)&pxz, g_xz);
    cudaGetSymbolAddress((void**)&pxh, g_xh);
    cudaGetSymbolAddress((void**)&pw1, g_w1h);
    cudaGetSymbolAddress((void**)&pw2, g_w2h);
    cudaGetSymbolAddress((void**)&pyh, g_ynh);

    cudaFuncSetAttribute(gemm_f16_pipe,
                         cudaFuncAttributeMaxDynamicSharedMemorySize,
                         PIPE_SMEM_BYTES);

    // 0) fp16 conversions of GEMM operands
    {
        int nx = (M_ROWS * DMODEL) / 4;
        cvt_a_f16_kernel<<<(nx + 255) / 256, 256>>>(x, pxh, nx);
        int nw1 = (DMODEL / 2) * (2 * DINNER / 4);
        cvt_w_f16_packed_kernel<<<(nw1 + 255) / 256, 256>>>(W_in, pw1, DMODEL, 2 * DINNER);
        int nw2 = (DINNER / 2) * (DMODEL / 4);
        cvt_w_f16_packed_kernel<<<(nw2 + 255) / 256, 256>>>(W_out, pw2, DINNER, DMODEL);
    }

    // 1) xz = x @ W_in   (fp16 mma k16 pipeline)
    dim3 g1(2 * DINNER / 128, M_ROWS / 128);
    gemm_f16_pipe<<<g1, 256, PIPE_SMEM_BYTES>>>(pxh, pw1, pxz,
                                                M_ROWS, 2 * DINNER, DMODEL);

    // 2) proj = silu(conv(xe)) @ W_xproj
    proj_conv_kernel<<<M_ROWS / 32, 256>>>(W_xproj, conv_w, conv_b);

    // 3) chunked scan
    scan_pass1<<<BATCH * NHEADS * NCHUNK, 128>>>(W_dt, b_dt, A_log, conv_w, conv_b);
    scan_pass2<<<(BATCH * NHEADS * HDIM * DSTATE) / 256, 256>>>();
    scan_pass3<<<BATCH * NHEADS * NCHUNK, 128>>>(W_dt, b_dt, A_log, D_skip, conv_w, conv_b);

    // 4) LN stats + apply + fp16 -> g_ynh
    ln_apply_kernel<<<M_ROWS, 256>>>(ln_g, ln_b);

    // 5) out = LN(y) @ W_out
    dim3 g2(DMODEL / 128, M_ROWS / 128);
    gemm_f16_pipe<<<g2, 256, PIPE_SMEM_BYTES>>>(pyh, pw2, out,
                                                M_ROWS, DMODEL, DINNER);
}

// round 16
// speedup vs baseline: 1.8244x; 1.1512x over previous
#include <cuda_runtime.h>
#include <cuda_fp16.h>
#include <math.h>
#include <stdint.h>

// ---------------------------------------------------------------------------
// Problem constants
// ---------------------------------------------------------------------------
#define BATCH   2
#define SEQ     4096
#define DMODEL  1024
#define DINNER  2048
#define NHEADS  16
#define HDIM    128
#define DSTATE  16
#define DCONV   4
#define CHUNK   64
#define NCHUNK  (SEQ / CHUNK)      // 64
#define M_ROWS  (BATCH * SEQ)      // 8192
#define NPROJ   (NHEADS + 2*DSTATE) // 48
#define ROWW    (2 * DINNER)        // g_xz row width
#define LN_EPS  1e-5f

// fp16 ldmatrix GEMM config: BM=BN=128, BK=64 halves, 8 warps 64x32, 3 stages
#define PSTAGES    3
#define TILE_B     (128 * 128)        // bytes per A or B stage (128 rows x 128B)
#define PIPE_SMEM_BYTES (2 * PSTAGES * TILE_B)   // 98304 B

// ---------------------------------------------------------------------------
// Scratch (static device globals -- no allocation allowed)
// ---------------------------------------------------------------------------
__device__ float  g_xz[(size_t)M_ROWS * ROWW];          // [xe | z]
__device__ float  g_proj[(size_t)M_ROWS * NPROJ];       // dt_raw | B | C
__device__ float  g_y[(size_t)M_ROWS * DINNER];         // raw gated y (pre-LN)
__device__ float  g_S[(size_t)BATCH*NHEADS*NCHUNK*HDIM*DSTATE];
__device__ float  g_Sin[(size_t)BATCH*NHEADS*NCHUNK*HDIM*DSTATE];
__device__ float  g_P[(size_t)BATCH*NHEADS*NCHUNK*HDIM];
__device__ __align__(16) __half g_xh [(size_t)M_ROWS * DMODEL];        // fp16 x
__device__ __align__(16) __half g_w1t[(size_t)(2*DINNER) * DMODEL];    // W_in^T  [N][K]
__device__ __align__(16) __half g_w2t[(size_t)DMODEL * DINNER];        // W_out^T [N][K]
__device__ __align__(16) __half g_ynh[(size_t)M_ROWS * DINNER];        // fp16 LN(y)

// ---------------------------------------------------------------------------
// Helpers
// ---------------------------------------------------------------------------
__device__ __forceinline__ void mma_f16(float* c, const uint32_t* a, const uint32_t* b) {
    asm volatile(
        "mma.sync.aligned.m16n8k16.row.col.f32.f16.f16.f32 "
        "{%0,%1,%2,%3},{%4,%5,%6,%7},{%8,%9},{%0,%1,%2,%3};"
        : "+f"(c[0]), "+f"(c[1]), "+f"(c[2]), "+f"(c[3])
        : "r"(a[0]), "r"(a[1]), "r"(a[2]), "r"(a[3]), "r"(b[0]), "r"(b[1]));
}
__device__ __forceinline__ void ldsm_x4(uint32_t* f, uint32_t addr) {
    asm volatile("ldmatrix.sync.aligned.m8n8.x4.shared.b16 {%0,%1,%2,%3}, [%4];"
                 : "=r"(f[0]), "=r"(f[1]), "=r"(f[2]), "=r"(f[3]) : "r"(addr));
}
__device__ __forceinline__ float softplus_f(float x) {
    return (x > 20.f) ? x : __logf(1.f + __expf(x));
}
__device__ __forceinline__ float silu_f(float v) {
    return v * __frcp_rn(1.f + __expf(-v));
}
__device__ __forceinline__ float4 ln_apply(float4 v, float mu, float rs,
                                           const float* __restrict__ g,
                                           const float* __restrict__ b, int col) {
    float4 gg = *(const float4*)(g + col);
    float4 bb = *(const float4*)(b + col);
    v.x = (v.x - mu) * rs * gg.x + bb.x;
    v.y = (v.y - mu) * rs * gg.y + bb.y;
    v.z = (v.z - mu) * rs * gg.z + bb.z;
    v.w = (v.w - mu) * rs * gg.w + bb.w;
    return v;
}
__device__ __forceinline__ uint32_t h2_bits(__half2 h) {
    return *reinterpret_cast<uint32_t*>(&h);
}
__device__ __forceinline__ void cp_async16(const void* smem_dst, const void* gmem_src) {
    uint32_t sa = (uint32_t)__cvta_generic_to_shared(smem_dst);
    asm volatile("cp.async.cg.shared.global [%0], [%1], 16;"
                 :: "r"(sa), "l"(gmem_src) : "memory");
}
#define CP_COMMIT()  asm volatile("cp.async.commit_group;" ::: "memory")
#define CP_WAIT1()   asm volatile("cp.async.wait_group 1;" ::: "memory")

// ---------------------------------------------------------------------------
// fp16 conversions.
// ---------------------------------------------------------------------------
__global__ __launch_bounds__(256) void cvt_a_f16_kernel(
    const float* __restrict__ src, __half* __restrict__ dst, int n4)
{
    int i = blockIdx.x * 256 + threadIdx.x;
    if (i < n4) {
        float4 v = ((const float4*)src)[i];
        __half2 h0 = __floats2half2_rn(v.x, v.y);
        __half2 h1 = __floats2half2_rn(v.z, v.w);
        ((uint2*)dst)[i] = make_uint2(h2_bits(h0), h2_bits(h1));
    }
}
// Transpose-convert: W [K][N] fp32 row-major -> Wt [N][K] fp16 row-major.
// grid (N/32, K/32), 256 threads (32x8), smem tile transpose.
__global__ __launch_bounds__(256) void cvt_w_f16_T_kernel(
    const float* __restrict__ W, __half* __restrict__ Wt, int Kdim, int Ndim)
{
    __shared__ float tile[32][33];
    const int n0 = blockIdx.x * 32, k0 = blockIdx.y * 32;
    const int tx = threadIdx.x & 31, ty = threadIdx.x >> 5;   // ty 0..7
#pragma unroll
    for (int i = 0; i < 4; i++) {
        int k = k0 + ty + i * 8;
        tile[ty + i * 8][tx] = W[(size_t)k * Ndim + n0 + tx];
    }
    __syncthreads();
#pragma unroll
    for (int i = 0; i < 4; i++) {
        int n = n0 + ty + i * 8;
        Wt[(size_t)n * Kdim + k0 + tx] = __float2half_rn(tile[tx][ty + i * 8]);
    }
}

// ---------------------------------------------------------------------------
// fp16 GEMM with ldmatrix fragments: C[M,N] = A[M,K] @ B[K,N], fp32 accum.
// A fp16 row-major [M][K]; Bt fp16 row-major transposed [N][K].
// BM=BN=128, BK=64 halves, 8 warps 64x32, 3-stage cp.async.
// Smem tiles: 128 rows x 128B (64 halves), XOR-swizzled (chunk ^= row&7).
// ---------------------------------------------------------------------------
__global__ __launch_bounds__(256, 2) void gemm_f16_ldsm(
    const __half* __restrict__ A, const __half* __restrict__ Bt,
    float* __restrict__ C, int M, int N, int K)
{
    extern __shared__ __align__(16) char sm[];
    char* Asm = sm;                         // [PSTAGES][128][128B]
    char* Bsm = sm + PSTAGES * TILE_B;      // [PSTAGES][128][128B]

    const int tid  = threadIdx.x;
    const int warp = tid >> 5, lane = tid & 31;
    const int wm   = (warp & 1) * 64;
    const int wn   = (warp >> 1) * 32;
    const int m0   = blockIdx.y * 128;
    const int n0   = blockIdx.x * 128;
    const int nk   = K >> 6;

    // staging: 1024 chunks per tile, 4 per thread; idx -> (row, chunk)
    auto stage = [&](int s, int kt) {
#pragma unroll
        for (int i = 0; i < 4; i++) {
            int idx = tid + i * 256;
            int r = idx >> 3, c = idx & 7;
            const __half* Ap = A + (size_t)(m0 + r) * K + kt * 64 + c * 8;
            const __half* Bp = Bt + (size_t)(n0 + r) * K + kt * 64 + c * 8;
            int off = r * 128 + ((c ^ (r & 7)) * 16);
            cp_async16(Asm + s * TILE_B + off, Ap);
            cp_async16(Bsm + s * TILE_B + off, Bp);
        }
    };

    stage(0, 0); CP_COMMIT();
    stage(1, 1); CP_COMMIT();

    float acc[4][4][4];
#pragma unroll
    for (int i = 0; i < 4; i++)
#pragma unroll
        for (int j = 0; j < 4; j++)
#pragma unroll
            for (int k = 0; k < 4; k++) acc[i][j][k] = 0.f;

    // ldmatrix per-lane address components (constant across kt)
    const int a_r = (lane & 15);            // + row base
    const int a_c = (lane >> 4);            // + 2*ks
    const int b_n = (lane & 7) + ((lane >> 4) << 3);
    const int b_c = ((lane >> 3) & 1);      // + 2*ks

    for (int kt = 0; kt < nk; kt++) {
        CP_WAIT1();
        __syncthreads();
        if (kt + 2 < nk) stage((kt + 2) % PSTAGES, kt + 2);
        CP_COMMIT();

        const char* Ac = Asm + (kt % PSTAGES) * TILE_B;
        const char* Bc = Bsm + (kt % PSTAGES) * TILE_B;

#pragma unroll
        for (int ks = 0; ks < 4; ks++) {
            uint32_t af[4][4], bf[2][4];
#pragma unroll
            for (int tm = 0; tm < 4; tm++) {
                int r = wm + tm * 16 + a_r;
                int c = 2 * ks + a_c;
                uint32_t ad = (uint32_t)__cvta_generic_to_shared(
                    Ac + r * 128 + ((c ^ (r & 7)) * 16));
                ldsm_x4(af[tm], ad);
            }
#pragma unroll
            for (int tg = 0; tg < 2; tg++) {
                int n = wn + tg * 16 + b_n;
                int c = 2 * ks + b_c;
                uint32_t bd = (uint32_t)__cvta_generic_to_shared(
                    Bc + n * 128 + ((c ^ (n & 7)) * 16));
                ldsm_x4(bf[tg], bd);
            }
#pragma unroll
            for (int tm = 0; tm < 4; tm++)
#pragma unroll
                for (int tn = 0; tn < 4; tn++)
                    mma_f16(acc[tm][tn], af[tm], &bf[tn >> 1][(tn & 1) * 2]);
        }
    }

    const int g = lane >> 2, q = lane & 3;
#pragma unroll
    for (int tm = 0; tm < 4; tm++) {
        const int row = m0 + wm + tm * 16 + g;
#pragma unroll
        for (int tn = 0; tn < 4; tn++) {
            const int col = n0 + wn + tn * 8 + 2 * q;
            *(float2*)&C[(size_t)row * N + col] =
                make_float2(acc[tm][tn][0], acc[tm][tn][1]);
            *(float2*)&C[(size_t)(row + 8) * N + col] =
                make_float2(acc[tm][tn][2], acc[tm][tn][3]);
        }
    }
}

// ---------------------------------------------------------------------------
// proj + fused depthwise conv + silu.
// ---------------------------------------------------------------------------
__global__ __launch_bounds__(256) void proj_conv_kernel(
    const float* __restrict__ W_xproj, const float* __restrict__ conv_w,
    const float* __restrict__ conv_b)
{
    __shared__ float xr[35][64];
    __shared__ float ws[64][NPROJ];
    __shared__ float xs[32][64];
    const int tid = threadIdx.x;
    const int m0  = blockIdx.x * 32;
    const bool seqstart = ((m0 & (SEQ - 1)) == 0);

    float acc[6];
#pragma unroll
    for (int o = 0; o < 6; o++) acc[o] = 0.f;

    for (int k0 = 0; k0 < DINNER; k0 += 64) {
        for (int t = tid; t < 35 * 64; t += 256) {
            int rr = t >> 6, cc = t & 63;
            float v = 0.f;
            if (!(seqstart && rr < 3))
                v = g_xz[(size_t)(m0 - 3 + rr) * ROWW + k0 + cc];
            xr[rr][cc] = v;
        }
        for (int t = tid; t < 64 * NPROJ; t += 256) {
            int kk = t / NPROJ;
            int j  = t - kk * NPROJ;
            ws[kk][j] = W_xproj[(size_t)(k0 + kk) * NPROJ + j];
        }
        __syncthreads();

        for (int t = tid; t < 32 * 64; t += 256) {
            int r  = t >> 6, cc = t & 63;
            int ch = k0 + cc;
            float4 wv = *(const float4*)(conv_w + (size_t)ch * 4);
            float a = conv_b[ch];
            a = fmaf(wv.x, xr[r][cc],     a);
            a = fmaf(wv.y, xr[r + 1][cc], a);
            a = fmaf(wv.z, xr[r + 2][cc], a);
            a = fmaf(wv.w, xr[r + 3][cc], a);
            xs[r][cc] = silu_f(a);
        }
        __syncthreads();

#pragma unroll
        for (int o = 0; o < 6; o++) {
            int oi = o * 256 + tid;
            int r  = oi / NPROJ;
            int j  = oi - r * NPROJ;
            float a = acc[o];
#pragma unroll 8
            for (int kk = 0; kk < 64; kk++)
                a = fmaf(xs[r][kk], ws[kk][j], a);
            acc[o] = a;
        }
        __syncthreads();
    }
#pragma unroll
    for (int o = 0; o < 6; o++) {
        int oi = o * 256 + tid;
        int r  = oi / NPROJ;
        int j  = oi - r * NPROJ;
        g_proj[(size_t)(m0 + r) * NPROJ + j] = acc[o];
    }
}

// ---------------------------------------------------------------------------
// Chunked scan, pass 1: rolling-window conv+silu, dt/decay on the fly.
// g_P is the PRODUCT of all 64 per-step decays.
// ---------------------------------------------------------------------------
__global__ __launch_bounds__(128) void scan_pass1(
    const float* __restrict__ W_dt, const float* __restrict__ b_dt,
    const float* __restrict__ A_log, const float* __restrict__ conv_w,
    const float* __restrict__ conv_b)
{
    const int blk = blockIdx.x;
    const int c   = blk & (NCHUNK - 1);
    const int h   = (blk >> 6) & (NHEADS - 1);
    const int b   = blk >> 10;
    const int d   = threadIdx.x;
    const int i   = h * HDIM + d;

    __shared__ float sB[CHUNK][DSTATE];
    __shared__ float sR[CHUNK][NHEADS];
    for (int t = threadIdx.x; t < CHUNK * DSTATE; t += 128) {
        int tt = t >> 4, n = t & 15;
        size_t pm = (size_t)(b * SEQ + c * CHUNK + tt) * NPROJ;
        sB[tt][n] = g_proj[pm + NHEADS + n];
        sR[tt][n] = g_proj[pm + n];
    }
    __syncthreads();

    float w[NHEADS];
#pragma unroll
    for (int hh = 0; hh < NHEADS; hh++) w[hh] = W_dt[(size_t)hh * DINNER + i];
    const float bd = b_dt[i];
    const float Ah = -__expf(A_log[h]);
    const float4 cw = *(const float4*)(conv_w + (size_t)i * 4);
    const float cb = conv_b[i];

    const int mbase = b * SEQ + c * CHUNK;
    float x3 = 0.f, x2 = 0.f, x1 = 0.f;
    if (c > 0) {
        x3 = g_xz[(size_t)(mbase - 3) * ROWW + i];
        x2 = g_xz[(size_t)(mbase - 2) * ROWW + i];
        x1 = g_xz[(size_t)(mbase - 1) * ROWW + i];
    }

    float s[DSTATE];
#pragma unroll
    for (int n = 0; n < DSTATE; n++) s[n] = 0.f;
    float cum = 0.f;
    float P   = 1.f;

    for (int tt = 0; tt < CHUNK; tt++) {
        float raw = bd;
#pragma unroll
        for (int hh = 0; hh < NHEADS; hh++) raw = fmaf(sR[tt][hh], w[hh], raw);
        float dtv = softplus_f(raw);
        cum += dtv;
        float a = __expf(Ah * cum);
        P *= a;

        float x0 = g_xz[(size_t)(mbase + tt) * ROWW + i];
        float cv = cb;
        cv = fmaf(cw.x, x3, cv);
        cv = fmaf(cw.y, x2, cv);
        cv = fmaf(cw.z, x1, cv);
        cv = fmaf(cw.w, x0, cv);
        float xc = silu_f(cv);
        x3 = x2; x2 = x1; x1 = x0;

        float u = dtv * xc;
#pragma unroll
        for (int n = 0; n < DSTATE; n++)
            s[n] = fmaf(s[n], a, u * sB[tt][n]);
    }
    const int base = ((b * NHEADS + h) * NCHUNK + c) * HDIM + d;
    g_P[base] = P;
#pragma unroll
    for (int n = 0; n < DSTATE; n++) g_S[(size_t)base * DSTATE + n] = s[n];
}

// ---------------------------------------------------------------------------
// Pass 2: stitch across chunks (separate in/out buffers -> pipelined loads).
// ---------------------------------------------------------------------------
__global__ __launch_bounds__(256) void scan_pass2()
{
    const int idx = blockIdx.x * 256 + threadIdx.x;
    const int n   = idx & (DSTATE - 1);
    const int d   = (idx >> 4) & (HDIM - 1);
    const int bh  = idx >> 11;

    float s = 0.f;
#pragma unroll 8
    for (int c = 0; c < NCHUNK; c++) {
        const int base = (bh * NCHUNK + c) * HDIM + d;
        const float Pv = g_P[base];
        const size_t off = (size_t)base * DSTATE + n;
        const float Sl = g_S[off];
        g_Sin[off] = s;
        s = fmaf(Pv, s, Sl);
    }
}

// ---------------------------------------------------------------------------
// Pass 3: replay (rolling conv) + y = C.s + D*x, gate with silu(z) -> g_y raw
// ---------------------------------------------------------------------------
__global__ __launch_bounds__(128) void scan_pass3(
    const float* __restrict__ W_dt, const float* __restrict__ b_dt,
    const float* __restrict__ A_log, const float* __restrict__ D_skip,
    const float* __restrict__ conv_w, const float* __restrict__ conv_b)
{
    const int blk = blockIdx.x;
    const int c   = blk & (NCHUNK - 1);
    const int h   = (blk >> 6) & (NHEADS - 1);
    const int b   = blk >> 10;
    const int d   = threadIdx.x;
    const int i   = h * HDIM + d;

    __shared__ float sB[CHUNK][DSTATE];
    __shared__ float sC[CHUNK][DSTATE];
    __shared__ float sR[CHUNK][NHEADS];
    for (int t = threadIdx.x; t < CHUNK * DSTATE; t += 128) {
        int tt = t >> 4, n = t & 15;
        size_t pm = (size_t)(b * SEQ + c * CHUNK + tt) * NPROJ;
        sB[tt][n] = g_proj[pm + NHEADS + n];
        sC[tt][n] = g_proj[pm + NHEADS + DSTATE + n];
        sR[tt][n] = g_proj[pm + n];
    }
    __syncthreads();

    float w[NHEADS];
#pragma unroll
    for (int hh = 0; hh < NHEADS; hh++) w[hh] = W_dt[(size_t)hh * DINNER + i];
    const float bd = b_dt[i];
    const float Ah = -__expf(A_log[h]);
    const float Dh = D_skip[h];
    const float4 cw = *(const float4*)(conv_w + (size_t)i * 4);
    const float cb = conv_b[i];

    const int base = ((b * NHEADS + h) * NCHUNK + c) * HDIM + d;
    float s[DSTATE];
#pragma unroll
    for (int n = 0; n < DSTATE; n++) s[n] = g_Sin[(size_t)base * DSTATE + n];

    const int mbase = b * SEQ + c * CHUNK;
    float x3 = 0.f, x2 = 0.f, x1 = 0.f;
    if (c > 0) {
        x3 = g_xz[(size_t)(mbase - 3) * ROWW + i];
        x2 = g_xz[(size_t)(mbase - 2) * ROWW + i];
        x1 = g_xz[(size_t)(mbase - 1) * ROWW + i];
    }

    float cum = 0.f;
    for (int tt = 0; tt < CHUNK; tt++) {
        float raw = bd;
#pragma unroll
        for (int hh = 0; hh < NHEADS; hh++) raw = fmaf(sR[tt][hh], w[hh], raw);
        float dtv = softplus_f(raw);
        cum += dtv;
        float a = __expf(Ah * cum);

        const size_t rowoff = (size_t)(mbase + tt) * ROWW;
        float x0 = g_xz[rowoff + i];
        float cv = cb;
        cv = fmaf(cw.x, x3, cv);
        cv = fmaf(cw.y, x2, cv);
        cv = fmaf(cw.z, x1, cv);
        cv = fmaf(cw.w, x0, cv);
        float xc = silu_f(cv);
        x3 = x2; x2 = x1; x1 = x0;

        float u = dtv * xc;
        float y = 0.f;
#pragma unroll
        for (int n = 0; n < DSTATE; n++) {
            s[n] = fmaf(s[n], a, u * sB[tt][n]);
            y    = fmaf(s[n], sC[tt][n], y);
        }
        y = fmaf(Dh, xc, y);
        float zv = g_xz[rowoff + DINNER + i];
        y *= silu_f(zv);
        g_y[(size_t)(mbase + tt) * DINNER + i] = y;
    }
}

// ---------------------------------------------------------------------------
// LayerNorm stats + apply + fp16 convert: g_y -> g_ynh (A operand of GEMM2).
// ---------------------------------------------------------------------------
__global__ __launch_bounds__(256) void ln_apply_kernel(
    const float* __restrict__ ln_g, const float* __restrict__ ln_b)
{
    __shared__ float sh[8];
    __shared__ float s_mu, s_rstd;
    const int m   = blockIdx.x;
    const int tid = threadIdx.x;
    const float* row = g_y + (size_t)m * DINNER;
    __half* rown = g_ynh + (size_t)m * DINNER;

    const int i0 = tid * 4;
    float4 a  = *(const float4*)(row + i0);
    float4 b4 = *(const float4*)(row + 1024 + i0);
    float v[8] = {a.x, a.y, a.z, a.w, b4.x, b4.y, b4.z, b4.w};

    float sum = 0.f;
#pragma unroll
    for (int k = 0; k < 8; k++) sum += v[k];
#pragma unroll
    for (int o = 16; o > 0; o >>= 1) sum += __shfl_xor_sync(0xffffffffu, sum, o);
    if ((tid & 31) == 0) sh[tid >> 5] = sum;
    __syncthreads();
    if (tid < 32) {
        float t = (tid < 8) ? sh[tid] : 0.f;
#pragma unroll
        for (int o = 4; o > 0; o >>= 1) t += __shfl_xor_sync(0xffffffffu, t, o);
        if (tid == 0) s_mu = t * (1.f / (float)DINNER);
    }
    __syncthreads();
    const float mu = s_mu;

    float var = 0.f;
#pragma unroll
    for (int k = 0; k < 8; k++) { float dv = v[k] - mu; var = fmaf(dv, dv, var); }
#pragma unroll
    for (int o = 16; o > 0; o >>= 1) var += __shfl_xor_sync(0xffffffffu, var, o);
    __syncthreads();
    if ((tid & 31) == 0) sh[tid >> 5] = var;
    __syncthreads();
    if (tid < 32) {
        float t = (tid < 8) ? sh[tid] : 0.f;
#pragma unroll
        for (int o = 4; o > 0; o >>= 1) t += __shfl_xor_sync(0xffffffffu, t, o);
        if (tid == 0) s_rstd = rsqrtf(t * (1.f / (float)DINNER) + LN_EPS);
    }
    __syncthreads();
    const float rs = s_rstd;

    float4 lo = ln_apply(make_float4(v[0], v[1], v[2], v[3]), mu, rs, ln_g, ln_b, i0);
    float4 hi = ln_apply(make_float4(v[4], v[5], v[6], v[7]), mu, rs, ln_g, ln_b, 1024 + i0);
    *(uint2*)(rown + i0) = make_uint2(
        h2_bits(__floats2half2_rn(lo.x, lo.y)), h2_bits(__floats2half2_rn(lo.z, lo.w)));
    *(uint2*)(rown + 1024 + i0) = make_uint2(
        h2_bits(__floats2half2_rn(hi.x, hi.y)), h2_bits(__floats2half2_rn(hi.z, hi.w)));
}

// ---------------------------------------------------------------------------
// kernel_launch
// ---------------------------------------------------------------------------
extern "C" void kernel_launch(void* const* d_in, const int* in_sizes, int n_in,
                              void* d_out, int out_size)
{
    const float* x       = (const float*)d_in[0];
    const float* W_in    = (const float*)d_in[1];
    const float* conv_w  = (const float*)d_in[2];
    const float* conv_b  = (const float*)d_in[3];
    const float* W_xproj = (const float*)d_in[4];
    const float* W_dt    = (const float*)d_in[5];
    const float* b_dt    = (const float*)d_in[6];
    const float* A_log   = (const float*)d_in[7];
    const float* D_skip  = (const float*)d_in[8];
    const float* W_out   = (const float*)d_in[9];
    const float* ln_g    = (const float*)d_in[10];
    const float* ln_b    = (const float*)d_in[11];
    float* out = (float*)d_out;

    float  *pxz = nullptr;
    __half *pxh = nullptr, *pyh = nullptr, *pw1 = nullptr, *pw2 = nullptr;
    cudaGetSymbolAddress((void**)&pxz, g_xz);
    cudaGetSymbolAddress((void**)&pxh, g_xh);
    cudaGetSymbolAddress((void**)&pw1, g_w1t);
    cudaGetSymbolAddress((void**)&pw2, g_w2t);
    cudaGetSymbolAddress((void**)&pyh, g_ynh);

    cudaFuncSetAttribute(gemm_f16_ldsm,
                         cudaFuncAttributeMaxDynamicSharedMemorySize,
                         PIPE_SMEM_BYTES);

    // 0) fp16 conversions: x row-major; weights transposed [N][K]
    {
        int nx = (M_ROWS * DMODEL) / 4;
        cvt_a_f16_kernel<<<(nx + 255) / 256, 256>>>(x, pxh, nx);
        dim3 gt1(2 * DINNER / 32, DMODEL / 32);
        cvt_w_f16_T_kernel<<<gt1, 256>>>(W_in, pw1, DMODEL, 2 * DINNER);
        dim3 gt2(DMODEL / 32, DINNER / 32);
        cvt_w_f16_T_kernel<<<gt2, 256>>>(W_out, pw2, DINNER, DMODEL);
    }

    // 1) xz = x @ W_in   (fp16 ldmatrix pipeline)
    dim3 g1(2 * DINNER / 128, M_ROWS / 128);
    gemm_f16_ldsm<<<g1, 256, PIPE_SMEM_BYTES>>>(pxh, pw1, pxz,
                                                M_ROWS, 2 * DINNER, DMODEL);

    // 2) proj = silu(conv(xe)) @ W_xproj
    proj_conv_kernel<<<M_ROWS / 32, 256>>>(W_xproj, conv_w, conv_b);

    // 3) chunked scan
    scan_pass1<<<BATCH * NHEADS * NCHUNK, 128>>>(W_dt, b_dt, A_log, conv_w, conv_b);
    scan_pass2<<<(BATCH * NHEADS * HDIM * DSTATE) / 256, 256>>>();
    scan_pass3<<<BATCH * NHEADS * NCHUNK, 128>>>(W_dt, b_dt, A_log, D_skip, conv_w, conv_b);

    // 4) LN stats + apply + fp16 -> g_ynh
    ln_apply_kernel<<<M_ROWS, 256>>>(ln_g, ln_b);

    // 5) out = LN(y) @ W_out
    dim3 g2(DMODEL / 128, M_ROWS / 128);
    gemm_f16_ldsm<<<g2, 256, PIPE_SMEM_BYTES>>>(pyh, pw2, out,
                                                M_ROWS, DMODEL, DINNER);
}

// round 17
// speedup vs baseline: 1.8653x; 1.0224x over previous
#include <cuda_runtime.h>
#include <cuda_fp16.h>
#include <math.h>
#include <stdint.h>

// ---------------------------------------------------------------------------
// Problem constants
// ---------------------------------------------------------------------------
#define BATCH   2
#define SEQ     4096
#define DMODEL  1024
#define DINNER  2048
#define NHEADS  16
#define HDIM    128
#define DSTATE  16
#define DCONV   4
#define CHUNK   64
#define NCHUNK  (SEQ / CHUNK)      // 64
#define M_ROWS  (BATCH * SEQ)      // 8192
#define NPROJ   (NHEADS + 2*DSTATE) // 48
#define ROWW    (2 * DINNER)        // g_xz row width
#define LN_EPS  1e-5f

// fp16 ldmatrix GEMM config: BM=BN=128, BK=64 halves, 8 warps 64x32, 3 stages
#define PSTAGES    3
#define TILE_B     (128 * 128)        // bytes per A or B stage (128 rows x 128B)
#define PIPE_SMEM_BYTES (2 * PSTAGES * TILE_B)   // 98304 B

// proj_conv config
#define PC_ROWS    64

// ---------------------------------------------------------------------------
// Scratch (static device globals -- no allocation allowed)
// ---------------------------------------------------------------------------
__device__ float  g_xz[(size_t)M_ROWS * ROWW];          // [xe | z]
__device__ float  g_proj[(size_t)M_ROWS * NPROJ];       // dt_raw | B | C
__device__ float  g_y[(size_t)M_ROWS * DINNER];         // raw gated y (pre-LN)
__device__ float  g_S[(size_t)BATCH*NHEADS*NCHUNK*HDIM*DSTATE];
__device__ float  g_Sin[(size_t)BATCH*NHEADS*NCHUNK*HDIM*DSTATE];
__device__ float  g_P[(size_t)BATCH*NHEADS*NCHUNK*HDIM];
__device__ __align__(16) __half g_xh [(size_t)M_ROWS * DMODEL];        // fp16 x
__device__ __align__(16) __half g_w1t[(size_t)(2*DINNER) * DMODEL];    // W_in^T  [N][K]
__device__ __align__(16) __half g_w2t[(size_t)DMODEL * DINNER];        // W_out^T [N][K]
__device__ __align__(16) __half g_ynh[(size_t)M_ROWS * DINNER];        // fp16 LN(y)

// ---------------------------------------------------------------------------
// Helpers
// ---------------------------------------------------------------------------
__device__ __forceinline__ void mma_f16(float* c, const uint32_t* a, const uint32_t* b) {
    asm volatile(
        "mma.sync.aligned.m16n8k16.row.col.f32.f16.f16.f32 "
        "{%0,%1,%2,%3},{%4,%5,%6,%7},{%8,%9},{%0,%1,%2,%3};"
        : "+f"(c[0]), "+f"(c[1]), "+f"(c[2]), "+f"(c[3])
        : "r"(a[0]), "r"(a[1]), "r"(a[2]), "r"(a[3]), "r"(b[0]), "r"(b[1]));
}
__device__ __forceinline__ void ldsm_x4(uint32_t* f, uint32_t addr) {
    asm volatile("ldmatrix.sync.aligned.m8n8.x4.shared.b16 {%0,%1,%2,%3}, [%4];"
                 : "=r"(f[0]), "=r"(f[1]), "=r"(f[2]), "=r"(f[3]) : "r"(addr));
}
__device__ __forceinline__ float softplus_f(float x) {
    return (x > 20.f) ? x : __logf(1.f + __expf(x));
}
__device__ __forceinline__ float silu_f(float v) {
    return v * __frcp_rn(1.f + __expf(-v));
}
__device__ __forceinline__ float4 ln_apply(float4 v, float mu, float rs,
                                           const float* __restrict__ g,
                                           const float* __restrict__ b, int col) {
    float4 gg = *(const float4*)(g + col);
    float4 bb = *(const float4*)(b + col);
    v.x = (v.x - mu) * rs * gg.x + bb.x;
    v.y = (v.y - mu) * rs * gg.y + bb.y;
    v.z = (v.z - mu) * rs * gg.z + bb.z;
    v.w = (v.w - mu) * rs * gg.w + bb.w;
    return v;
}
__device__ __forceinline__ uint32_t h2_bits(__half2 h) {
    return *reinterpret_cast<uint32_t*>(&h);
}
__device__ __forceinline__ void cp_async16(const void* smem_dst, const void* gmem_src) {
    uint32_t sa = (uint32_t)__cvta_generic_to_shared(smem_dst);
    asm volatile("cp.async.cg.shared.global [%0], [%1], 16;"
                 :: "r"(sa), "l"(gmem_src) : "memory");
}
#define CP_COMMIT()  asm volatile("cp.async.commit_group;" ::: "memory")
#define CP_WAIT1()   asm volatile("cp.async.wait_group 1;" ::: "memory")

// ---------------------------------------------------------------------------
// fp16 conversions.
// ---------------------------------------------------------------------------
__global__ __launch_bounds__(256) void cvt_a_f16_kernel(
    const float* __restrict__ src, __half* __restrict__ dst, int n4)
{
    int i = blockIdx.x * 256 + threadIdx.x;
    if (i < n4) {
        float4 v = ((const float4*)src)[i];
        __half2 h0 = __floats2half2_rn(v.x, v.y);
        __half2 h1 = __floats2half2_rn(v.z, v.w);
        ((uint2*)dst)[i] = make_uint2(h2_bits(h0), h2_bits(h1));
    }
}
// Transpose-convert: W [K][N] fp32 row-major -> Wt [N][K] fp16 row-major.
__global__ __launch_bounds__(256) void cvt_w_f16_T_kernel(
    const float* __restrict__ W, __half* __restrict__ Wt, int Kdim, int Ndim)
{
    __shared__ float tile[32][33];
    const int n0 = blockIdx.x * 32, k0 = blockIdx.y * 32;
    const int tx = threadIdx.x & 31, ty = threadIdx.x >> 5;   // ty 0..7
#pragma unroll
    for (int i = 0; i < 4; i++) {
        int k = k0 + ty + i * 8;
        tile[ty + i * 8][tx] = W[(size_t)k * Ndim + n0 + tx];
    }
    __syncthreads();
#pragma unroll
    for (int i = 0; i < 4; i++) {
        int n = n0 + ty + i * 8;
        Wt[(size_t)n * Kdim + k0 + tx] = __float2half_rn(tile[tx][ty + i * 8]);
    }
}

// ---------------------------------------------------------------------------
// fp16 GEMM with ldmatrix fragments (R16 measured-good config).
// ---------------------------------------------------------------------------
__global__ __launch_bounds__(256, 2) void gemm_f16_ldsm(
    const __half* __restrict__ A, const __half* __restrict__ Bt,
    float* __restrict__ C, int M, int N, int K)
{
    extern __shared__ __align__(16) char sm[];
    char* Asm = sm;                         // [PSTAGES][128][128B]
    char* Bsm = sm + PSTAGES * TILE_B;      // [PSTAGES][128][128B]

    const int tid  = threadIdx.x;
    const int warp = tid >> 5, lane = tid & 31;
    const int wm   = (warp & 1) * 64;
    const int wn   = (warp >> 1) * 32;
    const int m0   = blockIdx.y * 128;
    const int n0   = blockIdx.x * 128;
    const int nk   = K >> 6;

    auto stage = [&](int s, int kt) {
#pragma unroll
        for (int i = 0; i < 4; i++) {
            int idx = tid + i * 256;
            int r = idx >> 3, c = idx & 7;
            const __half* Ap = A + (size_t)(m0 + r) * K + kt * 64 + c * 8;
            const __half* Bp = Bt + (size_t)(n0 + r) * K + kt * 64 + c * 8;
            int off = r * 128 + ((c ^ (r & 7)) * 16);
            cp_async16(Asm + s * TILE_B + off, Ap);
            cp_async16(Bsm + s * TILE_B + off, Bp);
        }
    };

    stage(0, 0); CP_COMMIT();
    stage(1, 1); CP_COMMIT();

    float acc[4][4][4];
#pragma unroll
    for (int i = 0; i < 4; i++)
#pragma unroll
        for (int j = 0; j < 4; j++)
#pragma unroll
            for (int k = 0; k < 4; k++) acc[i][j][k] = 0.f;

    const int a_r = (lane & 15);
    const int a_c = (lane >> 4);
    const int b_n = (lane & 7) + ((lane >> 4) << 3);
    const int b_c = ((lane >> 3) & 1);

    for (int kt = 0; kt < nk; kt++) {
        CP_WAIT1();
        __syncthreads();
        if (kt + 2 < nk) stage((kt + 2) % PSTAGES, kt + 2);
        CP_COMMIT();

        const char* Ac = Asm + (kt % PSTAGES) * TILE_B;
        const char* Bc = Bsm + (kt % PSTAGES) * TILE_B;

#pragma unroll
        for (int ks = 0; ks < 4; ks++) {
            uint32_t af[4][4], bf[2][4];
#pragma unroll
            for (int tm = 0; tm < 4; tm++) {
                int r = wm + tm * 16 + a_r;
                int c = 2 * ks + a_c;
                uint32_t ad = (uint32_t)__cvta_generic_to_shared(
                    Ac + r * 128 + ((c ^ (r & 7)) * 16));
                ldsm_x4(af[tm], ad);
            }
#pragma unroll
            for (int tg = 0; tg < 2; tg++) {
                int n = wn + tg * 16 + b_n;
                int c = 2 * ks + b_c;
                uint32_t bd = (uint32_t)__cvta_generic_to_shared(
                    Bc + n * 128 + ((c ^ (n & 7)) * 16));
                ldsm_x4(bf[tg], bd);
            }
#pragma unroll
            for (int tm = 0; tm < 4; tm++)
#pragma unroll
                for (int tn = 0; tn < 4; tn++)
                    mma_f16(acc[tm][tn], af[tm], &bf[tn >> 1][(tn & 1) * 2]);
        }
    }

    const int g = lane >> 2, q = lane & 3;
#pragma unroll
    for (int tm = 0; tm < 4; tm++) {
        const int row = m0 + wm + tm * 16 + g;
#pragma unroll
        for (int tn = 0; tn < 4; tn++) {
            const int col = n0 + wn + tn * 8 + 2 * q;
            *(float2*)&C[(size_t)row * N + col] =
                make_float2(acc[tm][tn][0], acc[tm][tn][1]);
            *(float2*)&C[(size_t)(row + 8) * N + col] =
                make_float2(acc[tm][tn][2], acc[tm][tn][3]);
        }
    }
}

// ---------------------------------------------------------------------------
// proj + fused depthwise conv + silu, register-blocked.
// 64 rows/block, 256 threads as 16 row-groups x 16 col-groups; each thread
// accumulates a 4x3 output tile (12 FMA per 7 LDS vs 1 per 2 before).
// Accumulation order per output unchanged (kk ascending, tiles ascending)
// -> g_proj bit-identical.
// ---------------------------------------------------------------------------
__global__ __launch_bounds__(256) void proj_conv_kernel(
    const float* __restrict__ W_xproj, const float* __restrict__ conv_w,
    const float* __restrict__ conv_b)
{
    __shared__ float xr[PC_ROWS + 3][64];   // xe rows m0-3 .. m0+63, one k-tile
    __shared__ float ws[64][NPROJ];
    __shared__ float xs[PC_ROWS][65];       // conv+silu result, padded
    const int tid = threadIdx.x;
    const int m0  = blockIdx.x * PC_ROWS;
    const bool seqstart = ((m0 & (SEQ - 1)) == 0);

    const int rg = tid >> 4;       // 0..15 -> rows rg*4 .. rg*4+3
    const int jg = tid & 15;       // 0..15 -> cols jg*3 .. jg*3+2
    const int r0 = rg * 4;
    const int j0 = jg * 3;

    float acc[4][3];
#pragma unroll
    for (int i = 0; i < 4; i++)
#pragma unroll
        for (int c = 0; c < 3; c++) acc[i][c] = 0.f;

    for (int k0 = 0; k0 < DINNER; k0 += 64) {
        for (int t = tid; t < (PC_ROWS + 3) * 64; t += 256) {
            int rr = t >> 6, cc = t & 63;
            float v = 0.f;
            if (!(seqstart && rr < 3))
                v = g_xz[(size_t)(m0 - 3 + rr) * ROWW + k0 + cc];
            xr[rr][cc] = v;
        }
        for (int t = tid; t < 64 * NPROJ; t += 256) {
            int kk = t / NPROJ;
            int j  = t - kk * NPROJ;
            ws[kk][j] = W_xproj[(size_t)(k0 + kk) * NPROJ + j];
        }
        __syncthreads();

        for (int t = tid; t < PC_ROWS * 64; t += 256) {
            int r  = t >> 6, cc = t & 63;
            int ch = k0 + cc;
            float4 wv = *(const float4*)(conv_w + (size_t)ch * 4);
            float a = conv_b[ch];
            a = fmaf(wv.x, xr[r][cc],     a);
            a = fmaf(wv.y, xr[r + 1][cc], a);
            a = fmaf(wv.z, xr[r + 2][cc], a);
            a = fmaf(wv.w, xr[r + 3][cc], a);
            xs[r][cc] = silu_f(a);
        }
        __syncthreads();

#pragma unroll 8
        for (int kk = 0; kk < 64; kk++) {
            float xv0 = xs[r0 + 0][kk];
            float xv1 = xs[r0 + 1][kk];
            float xv2 = xs[r0 + 2][kk];
            float xv3 = xs[r0 + 3][kk];
            float w0 = ws[kk][j0 + 0];
            float w1 = ws[kk][j0 + 1];
            float w2 = ws[kk][j0 + 2];
            acc[0][0] = fmaf(xv0, w0, acc[0][0]);
            acc[0][1] = fmaf(xv0, w1, acc[0][1]);
            acc[0][2] = fmaf(xv0, w2, acc[0][2]);
            acc[1][0] = fmaf(xv1, w0, acc[1][0]);
            acc[1][1] = fmaf(xv1, w1, acc[1][1]);
            acc[1][2] = fmaf(xv1, w2, acc[1][2]);
            acc[2][0] = fmaf(xv2, w0, acc[2][0]);
            acc[2][1] = fmaf(xv2, w1, acc[2][1]);
            acc[2][2] = fmaf(xv2, w2, acc[2][2]);
            acc[3][0] = fmaf(xv3, w0, acc[3][0]);
            acc[3][1] = fmaf(xv3, w1, acc[3][1]);
            acc[3][2] = fmaf(xv3, w2, acc[3][2]);
        }
        __syncthreads();
    }

#pragma unroll
    for (int i = 0; i < 4; i++)
#pragma unroll
        for (int c = 0; c < 3; c++)
            g_proj[(size_t)(m0 + r0 + i) * NPROJ + j0 + c] = acc[i][c];
}

// ---------------------------------------------------------------------------
// Chunked scan, pass 1: rolling-window conv+silu, dt/decay on the fly.
// g_P is the PRODUCT of all 64 per-step decays.
// ---------------------------------------------------------------------------
__global__ __launch_bounds__(128) void scan_pass1(
    const float* __restrict__ W_dt, const float* __restrict__ b_dt,
    const float* __restrict__ A_log, const float* __restrict__ conv_w,
    const float* __restrict__ conv_b)
{
    const int blk = blockIdx.x;
    const int c   = blk & (NCHUNK - 1);
    const int h   = (blk >> 6) & (NHEADS - 1);
    const int b   = blk >> 10;
    const int d   = threadIdx.x;
    const int i   = h * HDIM + d;

    __shared__ float sB[CHUNK][DSTATE];
    __shared__ float sR[CHUNK][NHEADS];
    for (int t = threadIdx.x; t < CHUNK * DSTATE; t += 128) {
        int tt = t >> 4, n = t & 15;
        size_t pm = (size_t)(b * SEQ + c * CHUNK + tt) * NPROJ;
        sB[tt][n] = g_proj[pm + NHEADS + n];
        sR[tt][n] = g_proj[pm + n];
    }
    __syncthreads();

    float w[NHEADS];
#pragma unroll
    for (int hh = 0; hh < NHEADS; hh++) w[hh] = W_dt[(size_t)hh * DINNER + i];
    const float bd = b_dt[i];
    const float Ah = -__expf(A_log[h]);
    const float4 cw = *(const float4*)(conv_w + (size_t)i * 4);
    const float cb = conv_b[i];

    const int mbase = b * SEQ + c * CHUNK;
    float x3 = 0.f, x2 = 0.f, x1 = 0.f;
    if (c > 0) {
        x3 = g_xz[(size_t)(mbase - 3) * ROWW + i];
        x2 = g_xz[(size_t)(mbase - 2) * ROWW + i];
        x1 = g_xz[(size_t)(mbase - 1) * ROWW + i];
    }

    float s[DSTATE];
#pragma unroll
    for (int n = 0; n < DSTATE; n++) s[n] = 0.f;
    float cum = 0.f;
    float P   = 1.f;

    for (int tt = 0; tt < CHUNK; tt++) {
        float raw = bd;
#pragma unroll
        for (int hh = 0; hh < NHEADS; hh++) raw = fmaf(sR[tt][hh], w[hh], raw);
        float dtv = softplus_f(raw);
        cum += dtv;
        float a = __expf(Ah * cum);
        P *= a;

        float x0 = g_xz[(size_t)(mbase + tt) * ROWW + i];
        float cv = cb;
        cv = fmaf(cw.x, x3, cv);
        cv = fmaf(cw.y, x2, cv);
        cv = fmaf(cw.z, x1, cv);
        cv = fmaf(cw.w, x0, cv);
        float xc = silu_f(cv);
        x3 = x2; x2 = x1; x1 = x0;

        float u = dtv * xc;
#pragma unroll
        for (int n = 0; n < DSTATE; n++)
            s[n] = fmaf(s[n], a, u * sB[tt][n]);
    }
    const int base = ((b * NHEADS + h) * NCHUNK + c) * HDIM + d;
    g_P[base] = P;
#pragma unroll
    for (int n = 0; n < DSTATE; n++) g_S[(size_t)base * DSTATE + n] = s[n];
}

// ---------------------------------------------------------------------------
// Pass 2: stitch across chunks (separate in/out buffers -> pipelined loads).
// ---------------------------------------------------------------------------
__global__ __launch_bounds__(256) void scan_pass2()
{
    const int idx = blockIdx.x * 256 + threadIdx.x;
    const int n   = idx & (DSTATE - 1);
    const int d   = (idx >> 4) & (HDIM - 1);
    const int bh  = idx >> 11;

    float s = 0.f;
#pragma unroll 8
    for (int c = 0; c < NCHUNK; c++) {
        const int base = (bh * NCHUNK + c) * HDIM + d;
        const float Pv = g_P[base];
        const size_t off = (size_t)base * DSTATE + n;
        const float Sl = g_S[off];
        g_Sin[off] = s;
        s = fmaf(Pv, s, Sl);
    }
}

// ---------------------------------------------------------------------------
// Pass 3: replay (rolling conv) + y = C.s + D*x, gate with silu(z) -> g_y raw
// ---------------------------------------------------------------------------
__global__ __launch_bounds__(128) void scan_pass3(
    const float* __restrict__ W_dt, const float* __restrict__ b_dt,
    const float* __restrict__ A_log, const float* __restrict__ D_skip,
    const float* __restrict__ conv_w, const float* __restrict__ conv_b)
{
    const int blk = blockIdx.x;
    const int c   = blk & (NCHUNK - 1);
    const int h   = (blk >> 6) & (NHEADS - 1);
    const int b   = blk >> 10;
    const int d   = threadIdx.x;
    const int i   = h * HDIM + d;

    __shared__ float sB[CHUNK][DSTATE];
    __shared__ float sC[CHUNK][DSTATE];
    __shared__ float sR[CHUNK][NHEADS];
    for (int t = threadIdx.x; t < CHUNK * DSTATE; t += 128) {
        int tt = t >> 4, n = t & 15;
        size_t pm = (size_t)(b * SEQ + c * CHUNK + tt) * NPROJ;
        sB[tt][n] = g_proj[pm + NHEADS + n];
        sC[tt][n] = g_proj[pm + NHEADS + DSTATE + n];
        sR[tt][n] = g_proj[pm + n];
    }
    __syncthreads();

    float w[NHEADS];
#pragma unroll
    for (int hh = 0; hh < NHEADS; hh++) w[hh] = W_dt[(size_t)hh * DINNER + i];
    const float bd = b_dt[i];
    const float Ah = -__expf(A_log[h]);
    const float Dh = D_skip[h];
    const float4 cw = *(const float4*)(conv_w + (size_t)i * 4);
    const float cb = conv_b[i];

    const int base = ((b * NHEADS + h) * NCHUNK + c) * HDIM + d;
    float s[DSTATE];
#pragma unroll
    for (int n = 0; n < DSTATE; n++) s[n] = g_Sin[(size_t)base * DSTATE + n];

    const int mbase = b * SEQ + c * CHUNK;
    float x3 = 0.f, x2 = 0.f, x1 = 0.f;
    if (c > 0) {
        x3 = g_xz[(size_t)(mbase - 3) * ROWW + i];
        x2 = g_xz[(size_t)(mbase - 2) * ROWW + i];
        x1 = g_xz[(size_t)(mbase - 1) * ROWW + i];
    }

    float cum = 0.f;
    for (int tt = 0; tt < CHUNK; tt++) {
        float raw = bd;
#pragma unroll
        for (int hh = 0; hh < NHEADS; hh++) raw = fmaf(sR[tt][hh], w[hh], raw);
        float dtv = softplus_f(raw);
        cum += dtv;
        float a = __expf(Ah * cum);

        const size_t rowoff = (size_t)(mbase + tt) * ROWW;
        float x0 = g_xz[rowoff + i];
        float cv = cb;
        cv = fmaf(cw.x, x3, cv);
        cv = fmaf(cw.y, x2, cv);
        cv = fmaf(cw.z, x1, cv);
        cv = fmaf(cw.w, x0, cv);
        float xc = silu_f(cv);
        x3 = x2; x2 = x1; x1 = x0;

        float u = dtv * xc;
        float y = 0.f;
#pragma unroll
        for (int n = 0; n < DSTATE; n++) {
            s[n] = fmaf(s[n], a, u * sB[tt][n]);
            y    = fmaf(s[n], sC[tt][n], y);
        }
        y = fmaf(Dh, xc, y);
        float zv = g_xz[rowoff + DINNER + i];
        y *= silu_f(zv);
        g_y[(size_t)(mbase + tt) * DINNER + i] = y;
    }
}

// ---------------------------------------------------------------------------
// LayerNorm stats + apply + fp16 convert: g_y -> g_ynh (A operand of GEMM2).
// ---------------------------------------------------------------------------
__global__ __launch_bounds__(256) void ln_apply_kernel(
    const float* __restrict__ ln_g, const float* __restrict__ ln_b)
{
    __shared__ float sh[8];
    __shared__ float s_mu, s_rstd;
    const int m   = blockIdx.x;
    const int tid = threadIdx.x;
    const float* row = g_y + (size_t)m * DINNER;
    __half* rown = g_ynh + (size_t)m * DINNER;

    const int i0 = tid * 4;
    float4 a  = *(const float4*)(row + i0);
    float4 b4 = *(const float4*)(row + 1024 + i0);
    float v[8] = {a.x, a.y, a.z, a.w, b4.x, b4.y, b4.z, b4.w};

    float sum = 0.f;
#pragma unroll
    for (int k = 0; k < 8; k++) sum += v[k];
#pragma unroll
    for (int o = 16; o > 0; o >>= 1) sum += __shfl_xor_sync(0xffffffffu, sum, o);
    if ((tid & 31) == 0) sh[tid >> 5] = sum;
    __syncthreads();
    if (tid < 32) {
        float t = (tid < 8) ? sh[tid] : 0.f;
#pragma unroll
        for (int o = 4; o > 0; o >>= 1) t += __shfl_xor_sync(0xffffffffu, t, o);
        if (tid == 0) s_mu = t * (1.f / (float)DINNER);
    }
    __syncthreads();
    const float mu = s_mu;

    float var = 0.f;
#pragma unroll
    for (int k = 0; k < 8; k++) { float dv = v[k] - mu; var = fmaf(dv, dv, var); }
#pragma unroll
    for (int o = 16; o > 0; o >>= 1) var += __shfl_xor_sync(0xffffffffu, var, o);
    __syncthreads();
    if ((tid & 31) == 0) sh[tid >> 5] = var;
    __syncthreads();
    if (tid < 32) {
        float t = (tid < 8) ? sh[tid] : 0.f;
#pragma unroll
        for (int o = 4; o > 0; o >>= 1) t += __shfl_xor_sync(0xffffffffu, t, o);
        if (tid == 0) s_rstd = rsqrtf(t * (1.f / (float)DINNER) + LN_EPS);
    }
    __syncthreads();
    const float rs = s_rstd;

    float4 lo = ln_apply(make_float4(v[0], v[1], v[2], v[3]), mu, rs, ln_g, ln_b, i0);
    float4 hi = ln_apply(make_float4(v[4], v[5], v[6], v[7]), mu, rs, ln_g, ln_b, 1024 + i0);
    *(uint2*)(rown + i0) = make_uint2(
        h2_bits(__floats2half2_rn(lo.x, lo.y)), h2_bits(__floats2half2_rn(lo.z, lo.w)));
    *(uint2*)(rown + 1024 + i0) = make_uint2(
        h2_bits(__floats2half2_rn(hi.x, hi.y)), h2_bits(__floats2half2_rn(hi.z, hi.w)));
}

// ---------------------------------------------------------------------------
// kernel_launch
// ---------------------------------------------------------------------------
extern "C" void kernel_launch(void* const* d_in, const int* in_sizes, int n_in,
                              void* d_out, int out_size)
{
    const float* x       = (const float*)d_in[0];
    const float* W_in    = (const float*)d_in[1];
    const float* conv_w  = (const float*)d_in[2];
    const float* conv_b  = (const float*)d_in[3];
    const float* W_xproj = (const float*)d_in[4];
    const float* W_dt    = (const float*)d_in[5];
    const float* b_dt    = (const float*)d_in[6];
    const float* A_log   = (const float*)d_in[7];
    const float* D_skip  = (const float*)d_in[8];
    const float* W_out   = (const float*)d_in[9];
    const float* ln_g    = (const float*)d_in[10];
    const float* ln_b    = (const float*)d_in[11];
    float* out = (float*)d_out;

    float  *pxz = nullptr;
    __half *pxh = nullptr, *pyh = nullptr, *pw1 = nullptr, *pw2 = nullptr;
    cudaGetSymbolAddress((void**)&pxz, g_xz);
    cudaGetSymbolAddress((void**)&pxh, g_xh);
    cudaGetSymbolAddress((void**)&pw1, g_w1t);
    cudaGetSymbolAddress((void**)&pw2, g_w2t);
    cudaGetSymbolAddress((void**)&pyh, g_ynh);

    cudaFuncSetAttribute(gemm_f16_ldsm,
                         cudaFuncAttributeMaxDynamicSharedMemorySize,
                         PIPE_SMEM_BYTES);

    // 0) fp16 conversions: x row-major; weights transposed [N][K]
    {
        int nx = (M_ROWS * DMODEL) / 4;
        cvt_a_f16_kernel<<<(nx + 255) / 256, 256>>>(x, pxh, nx);
        dim3 gt1(2 * DINNER / 32, DMODEL / 32);
        cvt_w_f16_T_kernel<<<gt1, 256>>>(W_in, pw1, DMODEL, 2 * DINNER);
        dim3 gt2(DMODEL / 32, DINNER / 32);
        cvt_w_f16_T_kernel<<<gt2, 256>>>(W_out, pw2, DINNER, DMODEL);
    }

    // 1) xz = x @ W_in   (fp16 ldmatrix pipeline)
    dim3 g1(2 * DINNER / 128, M_ROWS / 128);
    gemm_f16_ldsm<<<g1, 256, PIPE_SMEM_BYTES>>>(pxh, pw1, pxz,
                                                M_ROWS, 2 * DINNER, DMODEL);

    // 2) proj = silu(conv(xe)) @ W_xproj  (register-blocked)
    proj_conv_kernel<<<M_ROWS / PC_ROWS, 256>>>(W_xproj, conv_w, conv_b);

    // 3) chunked scan
    scan_pass1<<<BATCH * NHEADS * NCHUNK, 128>>>(W_dt, b_dt, A_log, conv_w, conv_b);
    scan_pass2<<<(BATCH * NHEADS * HDIM * DSTATE) / 256, 256>>>();
    scan_pass3<<<BATCH * NHEADS * NCHUNK, 128>>>(W_dt, b_dt, A_log, D_skip, conv_w, conv_b);

    // 4) LN stats + apply + fp16 -> g_ynh
    ln_apply_kernel<<<M_ROWS, 256>>>(ln_g, ln_b);

    // 5) out = LN(y) @ W_out
    dim3 g2(DMODEL / 128, M_ROWS / 128);
    gemm_f16_ldsm<<<g2, 256, PIPE_SMEM_BYTES>>>(pyh, pw2, out,
                                                M_ROWS, DMODEL, DINNER);
}